// round 3
// baseline (speedup 1.0000x reference)
#include <cuda_runtime.h>
#include <cuda_bf16.h>

typedef unsigned long long ull;
#define FULL 0xffffffffu
#define NMAX 20000

// ---------------- scratch (static device globals; allocation-free) ----------
__device__ __align__(128) float g_s    [NMAX * 64];    // lin1 scalar out  [n][w]
__device__ __align__(128) float g_v    [NMAX * 192];   // lin1 vector out  [n][w][i]
__device__ __align__(128) float g_sc_s [NMAX * 128];   // self-conn scalar [n][w]
__device__ __align__(128) float g_sc_v [NMAX * 192];   // self-conn vector [n][w][i]
__device__ __align__(128) float g_s_agg[NMAX * 128];   // [n][u]  (0:63 oA, 64:127 oD)
__device__ __align__(128) float g_v_agg[NMAX * 384];   // [n][u][i] (u 0:63 oB, 64:127 oC)

// ---------------- helpers ----------------
__device__ __forceinline__ float silu_n(float x) {
    return 1.679177f * x * __fdividef(1.0f, 1.0f + __expf(-x));
}
__device__ __forceinline__ ull pack2(float x, float y) {
    ull r; asm("mov.b64 %0, {%1, %2};" : "=l"(r) : "f"(x), "f"(y)); return r;
}
__device__ __forceinline__ float2 unp2(ull a) {
    float2 r; asm("mov.b64 {%0, %1}, %2;" : "=f"(r.x), "=f"(r.y) : "l"(a)); return r;
}
__device__ __forceinline__ void ffma2(ull& d, ull a, ull b) {
    asm("fma.rn.f32x2 %0, %1, %2, %3;" : "=l"(d) : "l"(a), "l"(b), "l"(d));
}
__device__ __forceinline__ void redv4(float* p, float a, float b, float c, float d) {
    asm volatile("red.global.add.v4.f32 [%0], {%1, %2, %3, %4};"
                 :: "l"(p), "f"(a), "f"(b), "f"(c), "f"(d) : "memory");
}

// ======================= K0: zero aggregation buffers =======================
__global__ void k_zero(int n4s, int n4v) {
    int i = blockIdx.x * blockDim.x + threadIdx.x;
    float4 z = make_float4(0.f, 0.f, 0.f, 0.f);
    if (i < n4s) reinterpret_cast<float4*>(g_s_agg)[i] = z;
    if (i < n4v) reinterpret_cast<float4*>(g_v_agg)[i] = z;
}

// ======================= K1: node pre (lin1 + self-connection) ==============
// 256 threads, 16 nodes/block.  dyn smem = 82176 B.
__global__ __launch_bounds__(256, 2) void k_node_pre(
    const float* __restrict__ ns, const float* __restrict__ nv,
    const float* __restrict__ na,
    const float* __restrict__ W1s, const float* __restrict__ W1v,
    const float* __restrict__ Wscs, const float* __restrict__ Wscv)
{
    extern __shared__ float sm1[];
    float* sS    = sm1;           // 16*64         [n][k]
    float* sV    = sS + 1024;     // 16*3*64       [n][i][k]
    float* sAttr = sV + 3072;     // 16*4
    float* sAs   = sAttr + 64;    // 16*256        [n][u*4+v]
    float* sAv   = sAs + 4096;    // 16*3*256      [n][i][u*4+v]

    const int t  = threadIdx.x;
    const int n0 = blockIdx.x * 16;

    for (int i = t; i < 1024; i += 256) sS[i] = ns[(size_t)n0 * 64 + i];
    for (int i = t; i < 3072; i += 256) {
        int n = i / 192, r = i - n * 192, u = r / 3, c = r - u * 3;
        sV[n * 192 + c * 64 + u] = nv[(size_t)n0 * 192 + i];
    }
    if (t < 64) sAttr[t] = na[(size_t)n0 * 4 + t];
    __syncthreads();

    const int w = t & 63, g = t >> 6;   // 4 groups x 4 nodes

    // ---- lin1 scalar: s = ns @ W1s * (1/8) ----
    {
        float acc[4] = {0.f, 0.f, 0.f, 0.f};
        for (int k4 = 0; k4 < 64; k4 += 4) {
            float a0 = W1s[(k4 + 0) * 64 + w], a1 = W1s[(k4 + 1) * 64 + w];
            float a2 = W1s[(k4 + 2) * 64 + w], a3 = W1s[(k4 + 3) * 64 + w];
            #pragma unroll
            for (int n = 0; n < 4; n++) {
                float4 s4 = *reinterpret_cast<const float4*>(&sS[(g * 4 + n) * 64 + k4]);
                acc[n] += s4.x * a0 + s4.y * a1 + s4.z * a2 + s4.w * a3;
            }
        }
        #pragma unroll
        for (int n = 0; n < 4; n++)
            g_s[(size_t)(n0 + g * 4 + n) * 64 + w] = acc[n] * 0.125f;
    }
    // ---- lin1 vector ----
    {
        float acc[4][3];
        #pragma unroll
        for (int n = 0; n < 4; n++) { acc[n][0] = acc[n][1] = acc[n][2] = 0.f; }
        for (int k4 = 0; k4 < 64; k4 += 4) {
            float a0 = W1v[(k4 + 0) * 64 + w], a1 = W1v[(k4 + 1) * 64 + w];
            float a2 = W1v[(k4 + 2) * 64 + w], a3 = W1v[(k4 + 3) * 64 + w];
            #pragma unroll
            for (int n = 0; n < 4; n++)
                #pragma unroll
                for (int i = 0; i < 3; i++) {
                    float4 s4 = *reinterpret_cast<const float4*>(&sV[(g * 4 + n) * 192 + i * 64 + k4]);
                    acc[n][i] += s4.x * a0 + s4.y * a1 + s4.z * a2 + s4.w * a3;
                }
        }
        #pragma unroll
        for (int n = 0; n < 4; n++)
            #pragma unroll
            for (int i = 0; i < 3; i++)
                g_v[(size_t)(n0 + g * 4 + n) * 192 + w * 3 + i] = acc[n][i] * 0.125f;
    }
    // ---- outer products for self-connection ----
    for (int i = t; i < 4096; i += 256) {
        int n = i >> 8, uv = i & 255;
        sAs[i] = sS[n * 64 + (uv >> 2)] * sAttr[n * 4 + (uv & 3)];
    }
    for (int i = t; i < 12288; i += 256) {
        int n = i / 768, r = i - n * 768, c = r >> 8, uv = r & 255;
        sAv[i] = sV[n * 192 + c * 64 + (uv >> 2)] * sAttr[n * 4 + (uv & 3)];
    }
    __syncthreads();

    // ---- sc_s: (16,256)@(256,128) * 1/16 ----
    {
        const int w2 = t & 127, g2 = t >> 7;  // 2 groups x 8 nodes
        float acc[8];
        #pragma unroll
        for (int n = 0; n < 8; n++) acc[n] = 0.f;
        for (int k4 = 0; k4 < 256; k4 += 4) {
            float a0 = Wscs[(k4 + 0) * 128 + w2], a1 = Wscs[(k4 + 1) * 128 + w2];
            float a2 = Wscs[(k4 + 2) * 128 + w2], a3 = Wscs[(k4 + 3) * 128 + w2];
            #pragma unroll
            for (int n = 0; n < 8; n++) {
                float4 s4 = *reinterpret_cast<const float4*>(&sAs[(g2 * 8 + n) * 256 + k4]);
                acc[n] += s4.x * a0 + s4.y * a1 + s4.z * a2 + s4.w * a3;
            }
        }
        #pragma unroll
        for (int n = 0; n < 8; n++)
            g_sc_s[(size_t)(n0 + g2 * 8 + n) * 128 + w2] = acc[n] * 0.0625f;
    }
    // ---- sc_v: per i, (16,256)@(256,64) * 1/16 ----
    {
        float acc[4][3];
        #pragma unroll
        for (int n = 0; n < 4; n++) { acc[n][0] = acc[n][1] = acc[n][2] = 0.f; }
        for (int k4 = 0; k4 < 256; k4 += 4) {
            float a0 = Wscv[(k4 + 0) * 64 + w], a1 = Wscv[(k4 + 1) * 64 + w];
            float a2 = Wscv[(k4 + 2) * 64 + w], a3 = Wscv[(k4 + 3) * 64 + w];
            #pragma unroll
            for (int n = 0; n < 4; n++)
                #pragma unroll
                for (int i = 0; i < 3; i++) {
                    float4 s4 = *reinterpret_cast<const float4*>(&sAv[(g * 4 + n) * 768 + i * 256 + k4]);
                    acc[n][i] += s4.x * a0 + s4.y * a1 + s4.z * a2 + s4.w * a3;
                }
        }
        #pragma unroll
        for (int n = 0; n < 4; n++)
            #pragma unroll
            for (int i = 0; i < 3; i++)
                g_sc_v[(size_t)(n0 + g * 4 + n) * 192 + w * 3 + i] = acc[n][i] * 0.0625f;
    }
}

// ======================= K2: edge kernel (MLP + TP + scatter) ===============
// 256 threads (8 warps); each warp processes 4 edges/iter.  dyn smem 100352 B.
__global__ __launch_bounds__(256, 2) void k_edge(
    const float* __restrict__ emb, const float* __restrict__ esh,
    const int* __restrict__ esrc, const int* __restrict__ edst,
    const float* __restrict__ W0, const float* __restrict__ W1,
    const float* __restrict__ W2, int E)
{
    extern __shared__ float sm2[];
    float* sW2  = sm2;            // 16384
    float* sW1  = sm2 + 16384;    // 4096
    float* sW0_ = sm2 + 20480;    // 512
    float* sH0  = sm2 + 20992;    // 8 warps * 4 edges * 64
    float* sH1  = sm2 + 23040;    // same

    const int tid = threadIdx.x;
    for (int i = tid; i < 4096; i += 256)
        reinterpret_cast<float4*>(sW2)[i] = reinterpret_cast<const float4*>(W2)[i];
    for (int i = tid; i < 1024; i += 256)
        reinterpret_cast<float4*>(sW1)[i] = reinterpret_cast<const float4*>(W1)[i];
    for (int i = tid; i < 128; i += 256)
        reinterpret_cast<float4*>(sW0_)[i] = reinterpret_cast<const float4*>(W0)[i];
    __syncthreads();

    const int warp = tid >> 5, lane = tid & 31;
    float* sH0w = sH0 + warp * 256;
    float* sH1w = sH1 + warp * 256;
    const float RS8 = 0.35355339059327373f;   // 1/sqrt(8)
    const float I3  = 0.5773502691896258f;    // 1/sqrt(3)
    const int grp = lane >> 3;
    const int u0  = (lane & 7) * 8;

    const int nquad = (E + 3) >> 2;
    for (int q = blockIdx.x * 8 + warp; q < nquad; q += gridDim.x * 8) {
        const int e0 = q * 4;

        float embv = ((e0 + (lane >> 3)) < E) ? emb[(size_t)e0 * 8 + lane] : 0.f;
        float yv = 0.f;
        if (lane < 16) {
            int e = e0 + (lane >> 2);
            if (e < E) yv = esh[(size_t)e * 4 + (lane & 3)] * 0.0625f;  // fold 1/N_NEIGH
        }
        int idxv = 0;
        if (lane < 4)      { if (e0 + lane < E)     idxv = esrc[e0 + lane]; }
        else if (lane < 8) { if (e0 + lane - 4 < E) idxv = edst[e0 + lane - 4]; }

        // ---- stage1: h0 = silu_n(emb @ W0 / sqrt(8)), lane owns cols 2l,2l+1
        ull a1[4] = {0ull, 0ull, 0ull, 0ull};
        #pragma unroll
        for (int k = 0; k < 8; k++) {
            ull wp = *reinterpret_cast<const ull*>(&sW0_[k * 64 + 2 * lane]);
            #pragma unroll
            for (int e = 0; e < 4; e++) {
                float a = __shfl_sync(FULL, embv, e * 8 + k);
                ffma2(a1[e], pack2(a, a), wp);
            }
        }
        #pragma unroll
        for (int e = 0; e < 4; e++) {
            float2 p = unp2(a1[e]);
            *reinterpret_cast<float2*>(&sH0w[e * 64 + 2 * lane]) =
                make_float2(silu_n(p.x * RS8), silu_n(p.y * RS8));
        }
        __syncwarp();

        // ---- stage2: h1 = silu_n(h0 @ W1 / 8)
        ull a2[4] = {0ull, 0ull, 0ull, 0ull};
        #pragma unroll 4
        for (int k4 = 0; k4 < 64; k4 += 4) {
            float4 hc[4];
            #pragma unroll
            for (int e = 0; e < 4; e++)
                hc[e] = *reinterpret_cast<const float4*>(&sH0w[e * 64 + k4]);
            #pragma unroll
            for (int kk = 0; kk < 4; kk++) {
                ull wp = *reinterpret_cast<const ull*>(&sW1[(k4 + kk) * 64 + 2 * lane]);
                #pragma unroll
                for (int e = 0; e < 4; e++) {
                    float h = (kk == 0) ? hc[e].x : (kk == 1) ? hc[e].y : (kk == 2) ? hc[e].z : hc[e].w;
                    ffma2(a2[e], pack2(h, h), wp);
                }
            }
        }
        #pragma unroll
        for (int e = 0; e < 4; e++) {
            float2 p = unp2(a2[e]);
            *reinterpret_cast<float2*>(&sH1w[e * 64 + 2 * lane]) =
                make_float2(silu_n(p.x * 0.125f), silu_n(p.y * 0.125f));
        }
        __syncwarp();

        // ---- stage3: w = h1 @ W2 / 8, lane owns cols 8l..8l+7
        ull a3[4][4];
        #pragma unroll
        for (int e = 0; e < 4; e++)
            #pragma unroll
            for (int j = 0; j < 4; j++) a3[e][j] = 0ull;

        #pragma unroll 2
        for (int k4 = 0; k4 < 64; k4 += 4) {
            float4 hc[4];
            #pragma unroll
            for (int e = 0; e < 4; e++)
                hc[e] = *reinterpret_cast<const float4*>(&sH1w[e * 64 + k4]);
            #pragma unroll
            for (int kk = 0; kk < 4; kk++) {
                ulonglong2 wa = *reinterpret_cast<const ulonglong2*>(&sW2[(k4 + kk) * 256 + 8 * lane]);
                ulonglong2 wb = *reinterpret_cast<const ulonglong2*>(&sW2[(k4 + kk) * 256 + 8 * lane + 4]);
                #pragma unroll
                for (int e = 0; e < 4; e++) {
                    float h = (kk == 0) ? hc[e].x : (kk == 1) ? hc[e].y : (kk == 2) ? hc[e].z : hc[e].w;
                    ull hp = pack2(h, h);
                    ffma2(a3[e][0], hp, wa.x);
                    ffma2(a3[e][1], hp, wa.y);
                    ffma2(a3[e][2], hp, wb.x);
                    ffma2(a3[e][3], hp, wb.y);
                }
            }
        }

        // ---- tensor product + scatter ----
        #pragma unroll
        for (int e = 0; e < 4; e++) {
            if (e0 + e >= E) break;
            int src = __shfl_sync(FULL, idxv, e);
            int dst = __shfl_sync(FULL, idxv, 4 + e);
            float y0  = __shfl_sync(FULL, yv, e * 4 + 0);
            float y1x = __shfl_sync(FULL, yv, e * 4 + 1);
            float y1y = __shfl_sync(FULL, yv, e * 4 + 2);
            float y1z = __shfl_sync(FULL, yv, e * 4 + 3);
            float wr[8];
            #pragma unroll
            for (int j = 0; j < 4; j++) {
                float2 p = unp2(a3[e][j]);
                wr[2 * j] = p.x * 0.125f; wr[2 * j + 1] = p.y * 0.125f;
            }
            if (grp == 0) {                           // oA -> s_agg[:, u0..u0+7]
                float4 sa = *reinterpret_cast<const float4*>(&g_s[(size_t)src * 64 + u0]);
                float4 sb = *reinterpret_cast<const float4*>(&g_s[(size_t)src * 64 + u0 + 4]);
                float* p = &g_s_agg[(size_t)dst * 128 + u0];
                redv4(p,     wr[0] * sa.x * y0, wr[1] * sa.y * y0, wr[2] * sa.z * y0, wr[3] * sa.w * y0);
                redv4(p + 4, wr[4] * sb.x * y0, wr[5] * sb.y * y0, wr[6] * sb.z * y0, wr[7] * sb.w * y0);
            } else if (grp == 1) {                    // oB -> v_agg[:, u0..u0+7, :]
                float4 sa = *reinterpret_cast<const float4*>(&g_s[(size_t)src * 64 + u0]);
                float4 sb = *reinterpret_cast<const float4*>(&g_s[(size_t)src * 64 + u0 + 4]);
                float t0 = wr[0] * sa.x, t1 = wr[1] * sa.y, t2 = wr[2] * sa.z, t3 = wr[3] * sa.w;
                float t4 = wr[4] * sb.x, t5 = wr[5] * sb.y, t6 = wr[6] * sb.z, t7 = wr[7] * sb.w;
                float* p = &g_v_agg[(size_t)dst * 384 + u0 * 3];
                redv4(p,      t0 * y1x, t0 * y1y, t0 * y1z, t1 * y1x);
                redv4(p + 4,  t1 * y1y, t1 * y1z, t2 * y1x, t2 * y1y);
                redv4(p + 8,  t2 * y1z, t3 * y1x, t3 * y1y, t3 * y1z);
                redv4(p + 12, t4 * y1x, t4 * y1y, t4 * y1z, t5 * y1x);
                redv4(p + 16, t5 * y1y, t5 * y1z, t6 * y1x, t6 * y1y);
                redv4(p + 20, t6 * y1z, t7 * y1x, t7 * y1y, t7 * y1z);
            } else if (grp == 2) {                    // oC -> v_agg[:, 64+u0.., :]
                const float4* vp = reinterpret_cast<const float4*>(&g_v[(size_t)src * 192 + u0 * 3]);
                float vv[24];
                #pragma unroll
                for (int jj = 0; jj < 6; jj++) {
                    float4 qv = vp[jj];
                    vv[4 * jj] = qv.x; vv[4 * jj + 1] = qv.y; vv[4 * jj + 2] = qv.z; vv[4 * jj + 3] = qv.w;
                }
                float c[8];
                #pragma unroll
                for (int j = 0; j < 8; j++) c[j] = wr[j] * y0;
                float* p = &g_v_agg[(size_t)dst * 384 + 192 + u0 * 3];
                redv4(p,      c[0] * vv[0],  c[0] * vv[1],  c[0] * vv[2],  c[1] * vv[3]);
                redv4(p + 4,  c[1] * vv[4],  c[1] * vv[5],  c[2] * vv[6],  c[2] * vv[7]);
                redv4(p + 8,  c[2] * vv[8],  c[3] * vv[9],  c[3] * vv[10], c[3] * vv[11]);
                redv4(p + 12, c[4] * vv[12], c[4] * vv[13], c[4] * vv[14], c[5] * vv[15]);
                redv4(p + 16, c[5] * vv[16], c[5] * vv[17], c[6] * vv[18], c[6] * vv[19]);
                redv4(p + 20, c[6] * vv[20], c[7] * vv[21], c[7] * vv[22], c[7] * vv[23]);
            } else {                                  // oD -> s_agg[:, 64+u0..]
                const float4* vp = reinterpret_cast<const float4*>(&g_v[(size_t)src * 192 + u0 * 3]);
                float vv[24];
                #pragma unroll
                for (int jj = 0; jj < 6; jj++) {
                    float4 qv = vp[jj];
                    vv[4 * jj] = qv.x; vv[4 * jj + 1] = qv.y; vv[4 * jj + 2] = qv.z; vv[4 * jj + 3] = qv.w;
                }
                float o[8];
                #pragma unroll
                for (int j = 0; j < 8; j++) {
                    float d = vv[3 * j] * y1x + vv[3 * j + 1] * y1y + vv[3 * j + 2] * y1z;
                    o[j] = wr[j] * d * I3;
                }
                float* p = &g_s_agg[(size_t)dst * 128 + 64 + u0];
                redv4(p,     o[0], o[1], o[2], o[3]);
                redv4(p + 4, o[4], o[5], o[6], o[7]);
            }
        }
    }
}

// ======================= K3: node post (lin2 + sc + gating) =================
// 256 threads, 16 nodes/block.  dyn smem = 40960 B.
__global__ __launch_bounds__(256, 2) void k_node_post(
    const float* __restrict__ W2s, const float* __restrict__ W2v,
    float* __restrict__ out)
{
    extern __shared__ float sm3[];
    float* sSA = sm3;          // 16*128
    float* sVA = sm3 + 2048;   // 16*3*128  [n][i][u]
    float* sSH = sm3 + 8192;   // 16*128

    const int t  = threadIdx.x;
    const int n0 = blockIdx.x * 16;

    for (int i = t; i < 2048; i += 256) sSA[i] = g_s_agg[(size_t)n0 * 128 + i];
    for (int i = t; i < 6144; i += 256) {
        int n = i / 384, r = i - n * 384, u = r / 3, c = r - u * 3;
        sVA[n * 384 + c * 128 + u] = g_v_agg[(size_t)n0 * 384 + i];
    }
    __syncthreads();

    const float RS128 = 0.08838834764831845f;  // 1/sqrt(128)

    // ---- s_h = s_agg @ W_lin2_s * RS128 + sc_s ----
    {
        const int w2 = t & 127, g2 = t >> 7;
        float acc[8];
        #pragma unroll
        for (int n = 0; n < 8; n++) acc[n] = 0.f;
        for (int k4 = 0; k4 < 128; k4 += 4) {
            float a0 = W2s[(k4 + 0) * 128 + w2], a1 = W2s[(k4 + 1) * 128 + w2];
            float a2 = W2s[(k4 + 2) * 128 + w2], a3 = W2s[(k4 + 3) * 128 + w2];
            #pragma unroll
            for (int n = 0; n < 8; n++) {
                float4 s4 = *reinterpret_cast<const float4*>(&sSA[(g2 * 8 + n) * 128 + k4]);
                acc[n] += s4.x * a0 + s4.y * a1 + s4.z * a2 + s4.w * a3;
            }
        }
        #pragma unroll
        for (int n = 0; n < 8; n++) {
            int nn = n0 + g2 * 8 + n;
            float sh = acc[n] * RS128 + g_sc_s[(size_t)nn * 128 + w2];
            sSH[(g2 * 8 + n) * 128 + w2] = sh;
            if (w2 < 64) out[(size_t)nn * 256 + w2] = silu_n(sh);
        }
    }

    // ---- v_h = v_agg . W_lin2_v * RS128 + sc_v ----
    const int w = t & 63, g = t >> 6;
    float vh[4][3];
    #pragma unroll
    for (int n = 0; n < 4; n++) { vh[n][0] = vh[n][1] = vh[n][2] = 0.f; }
    for (int k4 = 0; k4 < 128; k4 += 4) {
        float a0 = W2v[(k4 + 0) * 64 + w], a1 = W2v[(k4 + 1) * 64 + w];
        float a2 = W2v[(k4 + 2) * 64 + w], a3 = W2v[(k4 + 3) * 64 + w];
        #pragma unroll
        for (int n = 0; n < 4; n++)
            #pragma unroll
            for (int i = 0; i < 3; i++) {
                float4 s4 = *reinterpret_cast<const float4*>(&sVA[(g * 4 + n) * 384 + i * 128 + k4]);
                vh[n][i] += s4.x * a0 + s4.y * a1 + s4.z * a2 + s4.w * a3;
            }
    }
    #pragma unroll
    for (int n = 0; n < 4; n++)
        #pragma unroll
        for (int i = 0; i < 3; i++)
            vh[n][i] = vh[n][i] * RS128 + g_sc_v[(size_t)(n0 + g * 4 + n) * 192 + w * 3 + i];
    __syncthreads();

    // ---- gated vector output ----
    #pragma unroll
    for (int n = 0; n < 4; n++) {
        int nn = n0 + g * 4 + n;
        float gate = silu_n(sSH[(g * 4 + n) * 128 + 64 + w]);
        out[(size_t)nn * 256 + 64 + w * 3 + 0] = gate * vh[n][0];
        out[(size_t)nn * 256 + 64 + w * 3 + 1] = gate * vh[n][1];
        out[(size_t)nn * 256 + 64 + w * 3 + 2] = gate * vh[n][2];
    }
}

// ======================= launcher ==========================================
extern "C" void kernel_launch(void* const* d_in, const int* in_sizes, int n_in,
                              void* d_out, int out_size) {
    const int N = in_sizes[0] / 64;
    const int E = in_sizes[3] / 4;

    const float *ns, *nv, *na, *esh, *emb;
    const float *W1s, *W1v, *W0, *W1, *W2, *W2s, *W2v, *Wscs, *Wscv;
    const int *esrc, *edst;

    ns  = (const float*)d_in[0];
    nv  = (const float*)d_in[1];
    na  = (const float*)d_in[2];
    esh = (const float*)d_in[3];
    emb = (const float*)d_in[4];
    if (in_sizes[5] == E && in_sizes[6] == E) {
        // dict order: edge_src, edge_dst right after edge_embedded
        esrc = (const int*)d_in[5];  edst = (const int*)d_in[6];
        W1s  = (const float*)d_in[7];  W1v  = (const float*)d_in[8];
        W0   = (const float*)d_in[9];  W1   = (const float*)d_in[10];
        W2   = (const float*)d_in[11]; W2s  = (const float*)d_in[12];
        W2v  = (const float*)d_in[13]; Wscs = (const float*)d_in[14];
        Wscv = (const float*)d_in[15];
    } else {
        // reference-arg order: weights first, indices last
        W1s  = (const float*)d_in[5];  W1v  = (const float*)d_in[6];
        W0   = (const float*)d_in[7];  W1   = (const float*)d_in[8];
        W2   = (const float*)d_in[9];  W2s  = (const float*)d_in[10];
        W2v  = (const float*)d_in[11]; Wscs = (const float*)d_in[12];
        Wscv = (const float*)d_in[13];
        esrc = (const int*)d_in[14];   edst = (const int*)d_in[15];
    }
    float* out = (float*)d_out;

    cudaFuncSetAttribute(k_edge,     cudaFuncAttributeMaxDynamicSharedMemorySize, 100352);
    cudaFuncSetAttribute(k_node_pre, cudaFuncAttributeMaxDynamicSharedMemorySize, 82176);

    int n4v = N * 96, n4s = N * 32;
    k_zero<<<(n4v + 255) / 256, 256>>>(n4s, n4v);
    k_node_pre<<<(N + 15) / 16, 256, 82176>>>(ns, nv, na, W1s, W1v, Wscs, Wscv);
    k_edge<<<296, 256, 100352>>>(emb, esh, esrc, edst, W0, W1, W2, E);
    k_node_post<<<(N + 15) / 16, 256, 40960>>>(W2s, W2v, out);
}

// round 4
// speedup vs baseline: 1.1250x; 1.1250x over previous
#include <cuda_runtime.h>
#include <cuda_bf16.h>

typedef unsigned long long ull;
#define FULL 0xffffffffu
#define NMAX 20000

// ---------------- scratch (static device globals; allocation-free) ----------
__device__ __align__(128) float g_s    [NMAX * 64];    // lin1 scalar out  [n][w]
__device__ __align__(128) float g_v    [NMAX * 192];   // lin1 vector out  [n][w][i]
__device__ __align__(128) float g_sc_s [NMAX * 128];   // self-conn scalar [n][w]
__device__ __align__(128) float g_sc_v [NMAX * 192];   // self-conn vector [n][w][i]
__device__ __align__(128) float g_s_agg[NMAX * 128];   // [n][u]  (0:63 oA, 64:127 oD)
__device__ __align__(128) float g_v_agg[NMAX * 384];   // [n][u][i] (u 0:63 oB, 64:127 oC)

// ---------------- helpers ----------------
__device__ __forceinline__ float silu_n(float x) {
    return 1.679177f * x * __fdividef(1.0f, 1.0f + __expf(-x));
}
__device__ __forceinline__ ull pack2(float x, float y) {
    ull r; asm("mov.b64 %0, {%1, %2};" : "=l"(r) : "f"(x), "f"(y)); return r;
}
__device__ __forceinline__ float2 unp2(ull a) {
    float2 r; asm("mov.b64 {%0, %1}, %2;" : "=f"(r.x), "=f"(r.y) : "l"(a)); return r;
}
__device__ __forceinline__ void ffma2(ull& d, ull a, ull b) {
    asm("fma.rn.f32x2 %0, %1, %2, %3;" : "=l"(d) : "l"(a), "l"(b), "l"(d));
}
__device__ __forceinline__ void redv4(float* p, float a, float b, float c, float d) {
    asm volatile("red.global.add.v4.f32 [%0], {%1, %2, %3, %4};"
                 :: "l"(p), "f"(a), "f"(b), "f"(c), "f"(d) : "memory");
}

// ======================= K0: zero aggregation buffers =======================
__global__ void k_zero(int n4s, int n4v) {
    int i = blockIdx.x * blockDim.x + threadIdx.x;
    float4 z = make_float4(0.f, 0.f, 0.f, 0.f);
    if (i < n4s) reinterpret_cast<float4*>(g_s_agg)[i] = z;
    if (i < n4v) reinterpret_cast<float4*>(g_v_agg)[i] = z;
}

// ======================= K1: node pre (lin1 + self-connection) ==============
// 256 threads, 16 nodes/block.  dyn smem = 82176 B.
__global__ __launch_bounds__(256, 2) void k_node_pre(
    const float* __restrict__ ns, const float* __restrict__ nv,
    const float* __restrict__ na,
    const float* __restrict__ W1s, const float* __restrict__ W1v,
    const float* __restrict__ Wscs, const float* __restrict__ Wscv)
{
    extern __shared__ float sm1[];
    float* sS    = sm1;           // 16*64         [n][k]
    float* sV    = sS + 1024;     // 16*3*64       [n][i][k]
    float* sAttr = sV + 3072;     // 16*4
    float* sAs   = sAttr + 64;    // 16*256        [n][u*4+v]
    float* sAv   = sAs + 4096;    // 16*3*256      [n][i][u*4+v]

    const int t  = threadIdx.x;
    const int n0 = blockIdx.x * 16;

    for (int i = t; i < 1024; i += 256) sS[i] = ns[(size_t)n0 * 64 + i];
    for (int i = t; i < 3072; i += 256) {
        int n = i / 192, r = i - n * 192, u = r / 3, c = r - u * 3;
        sV[n * 192 + c * 64 + u] = nv[(size_t)n0 * 192 + i];
    }
    if (t < 64) sAttr[t] = na[(size_t)n0 * 4 + t];
    __syncthreads();

    const int w = t & 63, g = t >> 6;   // 4 groups x 4 nodes

    // ---- lin1 scalar: s = ns @ W1s * (1/8) ----
    {
        float acc[4] = {0.f, 0.f, 0.f, 0.f};
        for (int k4 = 0; k4 < 64; k4 += 4) {
            float a0 = W1s[(k4 + 0) * 64 + w], a1 = W1s[(k4 + 1) * 64 + w];
            float a2 = W1s[(k4 + 2) * 64 + w], a3 = W1s[(k4 + 3) * 64 + w];
            #pragma unroll
            for (int n = 0; n < 4; n++) {
                float4 s4 = *reinterpret_cast<const float4*>(&sS[(g * 4 + n) * 64 + k4]);
                acc[n] += s4.x * a0 + s4.y * a1 + s4.z * a2 + s4.w * a3;
            }
        }
        #pragma unroll
        for (int n = 0; n < 4; n++)
            g_s[(size_t)(n0 + g * 4 + n) * 64 + w] = acc[n] * 0.125f;
    }
    // ---- lin1 vector ----
    {
        float acc[4][3];
        #pragma unroll
        for (int n = 0; n < 4; n++) { acc[n][0] = acc[n][1] = acc[n][2] = 0.f; }
        for (int k4 = 0; k4 < 64; k4 += 4) {
            float a0 = W1v[(k4 + 0) * 64 + w], a1 = W1v[(k4 + 1) * 64 + w];
            float a2 = W1v[(k4 + 2) * 64 + w], a3 = W1v[(k4 + 3) * 64 + w];
            #pragma unroll
            for (int n = 0; n < 4; n++)
                #pragma unroll
                for (int i = 0; i < 3; i++) {
                    float4 s4 = *reinterpret_cast<const float4*>(&sV[(g * 4 + n) * 192 + i * 64 + k4]);
                    acc[n][i] += s4.x * a0 + s4.y * a1 + s4.z * a2 + s4.w * a3;
                }
        }
        #pragma unroll
        for (int n = 0; n < 4; n++)
            #pragma unroll
            for (int i = 0; i < 3; i++)
                g_v[(size_t)(n0 + g * 4 + n) * 192 + w * 3 + i] = acc[n][i] * 0.125f;
    }
    // ---- outer products for self-connection ----
    for (int i = t; i < 4096; i += 256) {
        int n = i >> 8, uv = i & 255;
        sAs[i] = sS[n * 64 + (uv >> 2)] * sAttr[n * 4 + (uv & 3)];
    }
    for (int i = t; i < 12288; i += 256) {
        int n = i / 768, r = i - n * 768, c = r >> 8, uv = r & 255;
        sAv[i] = sV[n * 192 + c * 64 + (uv >> 2)] * sAttr[n * 4 + (uv & 3)];
    }
    __syncthreads();

    // ---- sc_s: (16,256)@(256,128) * 1/16 ----
    {
        const int w2 = t & 127, g2 = t >> 7;  // 2 groups x 8 nodes
        float acc[8];
        #pragma unroll
        for (int n = 0; n < 8; n++) acc[n] = 0.f;
        for (int k4 = 0; k4 < 256; k4 += 4) {
            float a0 = Wscs[(k4 + 0) * 128 + w2], a1 = Wscs[(k4 + 1) * 128 + w2];
            float a2 = Wscs[(k4 + 2) * 128 + w2], a3 = Wscs[(k4 + 3) * 128 + w2];
            #pragma unroll
            for (int n = 0; n < 8; n++) {
                float4 s4 = *reinterpret_cast<const float4*>(&sAs[(g2 * 8 + n) * 256 + k4]);
                acc[n] += s4.x * a0 + s4.y * a1 + s4.z * a2 + s4.w * a3;
            }
        }
        #pragma unroll
        for (int n = 0; n < 8; n++)
            g_sc_s[(size_t)(n0 + g2 * 8 + n) * 128 + w2] = acc[n] * 0.0625f;
    }
    // ---- sc_v: per i, (16,256)@(256,64) * 1/16 ----
    {
        float acc[4][3];
        #pragma unroll
        for (int n = 0; n < 4; n++) { acc[n][0] = acc[n][1] = acc[n][2] = 0.f; }
        for (int k4 = 0; k4 < 256; k4 += 4) {
            float a0 = Wscv[(k4 + 0) * 64 + w], a1 = Wscv[(k4 + 1) * 64 + w];
            float a2 = Wscv[(k4 + 2) * 64 + w], a3 = Wscv[(k4 + 3) * 64 + w];
            #pragma unroll
            for (int n = 0; n < 4; n++)
                #pragma unroll
                for (int i = 0; i < 3; i++) {
                    float4 s4 = *reinterpret_cast<const float4*>(&sAv[(g * 4 + n) * 768 + i * 256 + k4]);
                    acc[n][i] += s4.x * a0 + s4.y * a1 + s4.z * a2 + s4.w * a3;
                }
        }
        #pragma unroll
        for (int n = 0; n < 4; n++)
            #pragma unroll
            for (int i = 0; i < 3; i++)
                g_sc_v[(size_t)(n0 + g * 4 + n) * 192 + w * 3 + i] = acc[n][i] * 0.0625f;
    }
}

// ======================= K2: edge kernel (MLP + TP + scatter) ===============
// 256 threads (8 warps); each warp processes 8 edges/iter.  dyn smem 100352 B.
// Norm constants 1/sqrt(8), 1/8, 1/8 are folded into the staged weights.
__global__ __launch_bounds__(256, 2) void k_edge(
    const float* __restrict__ emb, const float* __restrict__ esh,
    const int* __restrict__ esrc, const int* __restrict__ edst,
    const float* __restrict__ W0, const float* __restrict__ W1,
    const float* __restrict__ W2, int E)
{
    extern __shared__ float sm2[];
    float* sW2  = sm2;            // 16384 floats (pre-scaled by 1/8)
    float* sW1  = sm2 + 16384;    // 4096  floats (pre-scaled by 1/8)
    float* sW0_ = sm2 + 20480;    // 512   floats (pre-scaled by 1/sqrt8)
    float* sH   = sm2 + 20992;    // 8 warps * 8 edges * 64 = 4096 floats

    const int tid = threadIdx.x;
    const float RS8 = 0.35355339059327373f;   // 1/sqrt(8)
    for (int i = tid; i < 4096; i += 256) {
        float4 v = reinterpret_cast<const float4*>(W2)[i];
        v.x *= 0.125f; v.y *= 0.125f; v.z *= 0.125f; v.w *= 0.125f;
        reinterpret_cast<float4*>(sW2)[i] = v;
    }
    for (int i = tid; i < 1024; i += 256) {
        float4 v = reinterpret_cast<const float4*>(W1)[i];
        v.x *= 0.125f; v.y *= 0.125f; v.z *= 0.125f; v.w *= 0.125f;
        reinterpret_cast<float4*>(sW1)[i] = v;
    }
    for (int i = tid; i < 128; i += 256) {
        float4 v = reinterpret_cast<const float4*>(W0)[i];
        v.x *= RS8; v.y *= RS8; v.z *= RS8; v.w *= RS8;
        reinterpret_cast<float4*>(sW0_)[i] = v;
    }
    __syncthreads();

    const int warp = tid >> 5, lane = tid & 31;
    float* sHw = sH + warp * 512;
    const float I3 = 0.5773502691896258f;    // 1/sqrt(3)
    const int grp = lane >> 3;
    const int u0  = (lane & 7) * 8;

    const int noct = (E + 7) >> 3;
    for (int q = blockIdx.x * 8 + warp; q < noct; q += gridDim.x * 8) {
        const int e0 = q * 8;

        // ---- per-octet loads (lane-distributed) ----
        // emb: 8 edges x 8 basis = 64 floats -> lane holds float2 for edge lane>>2
        ull embp = 0ull;
        {
            int e = e0 + (lane >> 2);
            if (e < E) {
                float2 v = *reinterpret_cast<const float2*>(&emb[(size_t)e0 * 8 + 2 * lane]);
                embp = pack2(v.x, v.y);
            }
        }
        // sh: 8 edges x 4 = 32 floats, fold 1/N_NEIGH
        float yv = 0.f;
        {
            int e = e0 + (lane >> 2);
            if (e < E) yv = esh[(size_t)e0 * 4 + lane] * 0.0625f;
        }
        // indices: lanes 0-7 src, 8-15 dst
        int idxv = 0;
        if (lane < 8)       { if (e0 + lane < E)     idxv = esrc[e0 + lane]; }
        else if (lane < 16) { if (e0 + lane - 8 < E) idxv = edst[e0 + lane - 8]; }

        // ---- stage1: h0 = silu_n(emb @ W0') ; lane owns cols 2l,2l+1 ----
        {
            ull a1[8];
            #pragma unroll
            for (int e = 0; e < 8; e++) a1[e] = 0ull;
            #pragma unroll
            for (int kp = 0; kp < 4; kp++) {
                ull w0 = *reinterpret_cast<const ull*>(&sW0_[(2 * kp) * 64 + 2 * lane]);
                ull w1 = *reinterpret_cast<const ull*>(&sW0_[(2 * kp + 1) * 64 + 2 * lane]);
                #pragma unroll
                for (int e = 0; e < 8; e++) {
                    float2 ab = unp2(__shfl_sync(FULL, embp, e * 4 + kp));
                    ffma2(a1[e], pack2(ab.x, ab.x), w0);
                    ffma2(a1[e], pack2(ab.y, ab.y), w1);
                }
            }
            #pragma unroll
            for (int e = 0; e < 8; e++) {
                float2 p = unp2(a1[e]);
                *reinterpret_cast<float2*>(&sHw[e * 64 + 2 * lane]) =
                    make_float2(silu_n(p.x), silu_n(p.y));
            }
        }
        __syncwarp();

        // ---- stage2: h1 = silu_n(h0 @ W1') ; in-place in sHw ----
        {
            ull a2[8];
            #pragma unroll
            for (int e = 0; e < 8; e++) a2[e] = 0ull;
            #pragma unroll 4
            for (int k4 = 0; k4 < 64; k4 += 4) {
                ull wp0 = *reinterpret_cast<const ull*>(&sW1[(k4 + 0) * 64 + 2 * lane]);
                ull wp1 = *reinterpret_cast<const ull*>(&sW1[(k4 + 1) * 64 + 2 * lane]);
                ull wp2 = *reinterpret_cast<const ull*>(&sW1[(k4 + 2) * 64 + 2 * lane]);
                ull wp3 = *reinterpret_cast<const ull*>(&sW1[(k4 + 3) * 64 + 2 * lane]);
                #pragma unroll
                for (int e = 0; e < 8; e++) {
                    float4 hc = *reinterpret_cast<const float4*>(&sHw[e * 64 + k4]);
                    ffma2(a2[e], pack2(hc.x, hc.x), wp0);
                    ffma2(a2[e], pack2(hc.y, hc.y), wp1);
                    ffma2(a2[e], pack2(hc.z, hc.z), wp2);
                    ffma2(a2[e], pack2(hc.w, hc.w), wp3);
                }
            }
            __syncwarp();   // all reads of h0 complete before overwrite
            #pragma unroll
            for (int e = 0; e < 8; e++) {
                float2 p = unp2(a2[e]);
                *reinterpret_cast<float2*>(&sHw[e * 64 + 2 * lane]) =
                    make_float2(silu_n(p.x), silu_n(p.y));
            }
        }
        __syncwarp();

        // ---- stage3: w = h1 @ W2' ; lane owns cols 8l..8l+7 ----
        ull a3[8][4];
        #pragma unroll
        for (int e = 0; e < 8; e++)
            #pragma unroll
            for (int j = 0; j < 4; j++) a3[e][j] = 0ull;

        for (int k4 = 0; k4 < 64; k4 += 4) {
            float4 hc[8];
            #pragma unroll
            for (int e = 0; e < 8; e++)
                hc[e] = *reinterpret_cast<const float4*>(&sHw[e * 64 + k4]);
            #pragma unroll
            for (int kk = 0; kk < 4; kk++) {
                ulonglong2 wa = *reinterpret_cast<const ulonglong2*>(&sW2[(k4 + kk) * 256 + 8 * lane]);
                ulonglong2 wb = *reinterpret_cast<const ulonglong2*>(&sW2[(k4 + kk) * 256 + 8 * lane + 4]);
                #pragma unroll
                for (int e = 0; e < 8; e++) {
                    float h = (kk == 0) ? hc[e].x : (kk == 1) ? hc[e].y : (kk == 2) ? hc[e].z : hc[e].w;
                    ull hp = pack2(h, h);
                    ffma2(a3[e][0], hp, wa.x);
                    ffma2(a3[e][1], hp, wa.y);
                    ffma2(a3[e][2], hp, wb.x);
                    ffma2(a3[e][3], hp, wb.y);
                }
            }
        }

        // ---- tensor product + scatter ----
        #pragma unroll
        for (int e = 0; e < 8; e++) {
            if (e0 + e >= E) break;
            int src = __shfl_sync(FULL, idxv, e);
            int dst = __shfl_sync(FULL, idxv, 8 + e);
            float y0  = __shfl_sync(FULL, yv, e * 4 + 0);
            float y1x = __shfl_sync(FULL, yv, e * 4 + 1);
            float y1y = __shfl_sync(FULL, yv, e * 4 + 2);
            float y1z = __shfl_sync(FULL, yv, e * 4 + 3);
            float wr[8];
            #pragma unroll
            for (int j = 0; j < 4; j++) {
                float2 p = unp2(a3[e][j]);
                wr[2 * j] = p.x; wr[2 * j + 1] = p.y;
            }
            if (grp == 0) {                           // oA -> s_agg[:, u0..u0+7]
                float4 sa = *reinterpret_cast<const float4*>(&g_s[(size_t)src * 64 + u0]);
                float4 sb = *reinterpret_cast<const float4*>(&g_s[(size_t)src * 64 + u0 + 4]);
                float* p = &g_s_agg[(size_t)dst * 128 + u0];
                redv4(p,     wr[0] * sa.x * y0, wr[1] * sa.y * y0, wr[2] * sa.z * y0, wr[3] * sa.w * y0);
                redv4(p + 4, wr[4] * sb.x * y0, wr[5] * sb.y * y0, wr[6] * sb.z * y0, wr[7] * sb.w * y0);
            } else if (grp == 1) {                    // oB -> v_agg[:, u0..u0+7, :]
                float4 sa = *reinterpret_cast<const float4*>(&g_s[(size_t)src * 64 + u0]);
                float4 sb = *reinterpret_cast<const float4*>(&g_s[(size_t)src * 64 + u0 + 4]);
                float t0 = wr[0] * sa.x, t1 = wr[1] * sa.y, t2 = wr[2] * sa.z, t3 = wr[3] * sa.w;
                float t4 = wr[4] * sb.x, t5 = wr[5] * sb.y, t6 = wr[6] * sb.z, t7 = wr[7] * sb.w;
                float* p = &g_v_agg[(size_t)dst * 384 + u0 * 3];
                redv4(p,      t0 * y1x, t0 * y1y, t0 * y1z, t1 * y1x);
                redv4(p + 4,  t1 * y1y, t1 * y1z, t2 * y1x, t2 * y1y);
                redv4(p + 8,  t2 * y1z, t3 * y1x, t3 * y1y, t3 * y1z);
                redv4(p + 12, t4 * y1x, t4 * y1y, t4 * y1z, t5 * y1x);
                redv4(p + 16, t5 * y1y, t5 * y1z, t6 * y1x, t6 * y1y);
                redv4(p + 20, t6 * y1z, t7 * y1x, t7 * y1y, t7 * y1z);
            } else if (grp == 2) {                    // oC -> v_agg[:, 64+u0.., :]
                const float4* vp = reinterpret_cast<const float4*>(&g_v[(size_t)src * 192 + u0 * 3]);
                float vv[24];
                #pragma unroll
                for (int jj = 0; jj < 6; jj++) {
                    float4 qv = vp[jj];
                    vv[4 * jj] = qv.x; vv[4 * jj + 1] = qv.y; vv[4 * jj + 2] = qv.z; vv[4 * jj + 3] = qv.w;
                }
                float c[8];
                #pragma unroll
                for (int j = 0; j < 8; j++) c[j] = wr[j] * y0;
                float* p = &g_v_agg[(size_t)dst * 384 + 192 + u0 * 3];
                redv4(p,      c[0] * vv[0],  c[0] * vv[1],  c[0] * vv[2],  c[1] * vv[3]);
                redv4(p + 4,  c[1] * vv[4],  c[1] * vv[5],  c[2] * vv[6],  c[2] * vv[7]);
                redv4(p + 8,  c[2] * vv[8],  c[3] * vv[9],  c[3] * vv[10], c[3] * vv[11]);
                redv4(p + 12, c[4] * vv[12], c[4] * vv[13], c[4] * vv[14], c[5] * vv[15]);
                redv4(p + 16, c[5] * vv[16], c[5] * vv[17], c[6] * vv[18], c[6] * vv[19]);
                redv4(p + 20, c[6] * vv[20], c[7] * vv[21], c[7] * vv[22], c[7] * vv[23]);
            } else {                                  // oD -> s_agg[:, 64+u0..]
                const float4* vp = reinterpret_cast<const float4*>(&g_v[(size_t)src * 192 + u0 * 3]);
                float vv[24];
                #pragma unroll
                for (int jj = 0; jj < 6; jj++) {
                    float4 qv = vp[jj];
                    vv[4 * jj] = qv.x; vv[4 * jj + 1] = qv.y; vv[4 * jj + 2] = qv.z; vv[4 * jj + 3] = qv.w;
                }
                float o[8];
                #pragma unroll
                for (int j = 0; j < 8; j++) {
                    float d = vv[3 * j] * y1x + vv[3 * j + 1] * y1y + vv[3 * j + 2] * y1z;
                    o[j] = wr[j] * d * I3;
                }
                float* p = &g_s_agg[(size_t)dst * 128 + 64 + u0];
                redv4(p,     o[0], o[1], o[2], o[3]);
                redv4(p + 4, o[4], o[5], o[6], o[7]);
            }
        }
    }
}

// ======================= K3: node post (lin2 + sc + gating) =================
// 256 threads, 16 nodes/block.  dyn smem = 40960 B.
__global__ __launch_bounds__(256, 2) void k_node_post(
    const float* __restrict__ W2s, const float* __restrict__ W2v,
    float* __restrict__ out)
{
    extern __shared__ float sm3[];
    float* sSA = sm3;          // 16*128
    float* sVA = sm3 + 2048;   // 16*3*128  [n][i][u]
    float* sSH = sm3 + 8192;   // 16*128

    const int t  = threadIdx.x;
    const int n0 = blockIdx.x * 16;

    for (int i = t; i < 2048; i += 256) sSA[i] = g_s_agg[(size_t)n0 * 128 + i];
    for (int i = t; i < 6144; i += 256) {
        int n = i / 384, r = i - n * 384, u = r / 3, c = r - u * 3;
        sVA[n * 384 + c * 128 + u] = g_v_agg[(size_t)n0 * 384 + i];
    }
    __syncthreads();

    const float RS128 = 0.08838834764831845f;  // 1/sqrt(128)

    // ---- s_h = s_agg @ W_lin2_s * RS128 + sc_s ----
    {
        const int w2 = t & 127, g2 = t >> 7;
        float acc[8];
        #pragma unroll
        for (int n = 0; n < 8; n++) acc[n] = 0.f;
        for (int k4 = 0; k4 < 128; k4 += 4) {
            float a0 = W2s[(k4 + 0) * 128 + w2], a1 = W2s[(k4 + 1) * 128 + w2];
            float a2 = W2s[(k4 + 2) * 128 + w2], a3 = W2s[(k4 + 3) * 128 + w2];
            #pragma unroll
            for (int n = 0; n < 8; n++) {
                float4 s4 = *reinterpret_cast<const float4*>(&sSA[(g2 * 8 + n) * 128 + k4]);
                acc[n] += s4.x * a0 + s4.y * a1 + s4.z * a2 + s4.w * a3;
            }
        }
        #pragma unroll
        for (int n = 0; n < 8; n++) {
            int nn = n0 + g2 * 8 + n;
            float sh = acc[n] * RS128 + g_sc_s[(size_t)nn * 128 + w2];
            sSH[(g2 * 8 + n) * 128 + w2] = sh;
            if (w2 < 64) out[(size_t)nn * 256 + w2] = silu_n(sh);
        }
    }

    // ---- v_h = v_agg . W_lin2_v * RS128 + sc_v ----
    const int w = t & 63, g = t >> 6;
    float vh[4][3];
    #pragma unroll
    for (int n = 0; n < 4; n++) { vh[n][0] = vh[n][1] = vh[n][2] = 0.f; }
    for (int k4 = 0; k4 < 128; k4 += 4) {
        float a0 = W2v[(k4 + 0) * 64 + w], a1 = W2v[(k4 + 1) * 64 + w];
        float a2 = W2v[(k4 + 2) * 64 + w], a3 = W2v[(k4 + 3) * 64 + w];
        #pragma unroll
        for (int n = 0; n < 4; n++)
            #pragma unroll
            for (int i = 0; i < 3; i++) {
                float4 s4 = *reinterpret_cast<const float4*>(&sVA[(g * 4 + n) * 384 + i * 128 + k4]);
                vh[n][i] += s4.x * a0 + s4.y * a1 + s4.z * a2 + s4.w * a3;
            }
    }
    #pragma unroll
    for (int n = 0; n < 4; n++)
        #pragma unroll
        for (int i = 0; i < 3; i++)
            vh[n][i] = vh[n][i] * RS128 + g_sc_v[(size_t)(n0 + g * 4 + n) * 192 + w * 3 + i];
    __syncthreads();

    // ---- gated vector output ----
    #pragma unroll
    for (int n = 0; n < 4; n++) {
        int nn = n0 + g * 4 + n;
        float gate = silu_n(sSH[(g * 4 + n) * 128 + 64 + w]);
        out[(size_t)nn * 256 + 64 + w * 3 + 0] = gate * vh[n][0];
        out[(size_t)nn * 256 + 64 + w * 3 + 1] = gate * vh[n][1];
        out[(size_t)nn * 256 + 64 + w * 3 + 2] = gate * vh[n][2];
    }
}

// ======================= launcher ==========================================
extern "C" void kernel_launch(void* const* d_in, const int* in_sizes, int n_in,
                              void* d_out, int out_size) {
    const int N = in_sizes[0] / 64;
    const int E = in_sizes[3] / 4;

    const float *ns, *nv, *na, *esh, *emb;
    const float *W1s, *W1v, *W0, *W1, *W2, *W2s, *W2v, *Wscs, *Wscv;
    const int *esrc, *edst;

    ns  = (const float*)d_in[0];
    nv  = (const float*)d_in[1];
    na  = (const float*)d_in[2];
    esh = (const float*)d_in[3];
    emb = (const float*)d_in[4];
    if (in_sizes[5] == E && in_sizes[6] == E) {
        esrc = (const int*)d_in[5];  edst = (const int*)d_in[6];
        W1s  = (const float*)d_in[7];  W1v  = (const float*)d_in[8];
        W0   = (const float*)d_in[9];  W1   = (const float*)d_in[10];
        W2   = (const float*)d_in[11]; W2s  = (const float*)d_in[12];
        W2v  = (const float*)d_in[13]; Wscs = (const float*)d_in[14];
        Wscv = (const float*)d_in[15];
    } else {
        W1s  = (const float*)d_in[5];  W1v  = (const float*)d_in[6];
        W0   = (const float*)d_in[7];  W1   = (const float*)d_in[8];
        W2   = (const float*)d_in[9];  W2s  = (const float*)d_in[10];
        W2v  = (const float*)d_in[11]; Wscs = (const float*)d_in[12];
        Wscv = (const float*)d_in[13];
        esrc = (const int*)d_in[14];   edst = (const int*)d_in[15];
    }
    float* out = (float*)d_out;

    cudaFuncSetAttribute(k_edge,     cudaFuncAttributeMaxDynamicSharedMemorySize, 100352);
    cudaFuncSetAttribute(k_node_pre, cudaFuncAttributeMaxDynamicSharedMemorySize, 82176);

    int n4v = N * 96, n4s = N * 32;
    k_zero<<<(n4v + 255) / 256, 256>>>(n4s, n4v);
    k_node_pre<<<(N + 15) / 16, 256, 82176>>>(ns, nv, na, W1s, W1v, Wscs, Wscv);
    k_edge<<<296, 256, 100352>>>(emb, esh, esrc, edst, W0, W1, W2, E);
    k_node_post<<<(N + 15) / 16, 256, 40960>>>(W2s, W2v, out);
}

// round 5
// speedup vs baseline: 1.4035x; 1.2475x over previous
#include <cuda_runtime.h>
#include <cuda_bf16.h>

typedef unsigned long long ull;
#define FULL 0xffffffffu
#define NMAX 20000

// ---------------- scratch (static device globals; allocation-free) ----------
__device__ __align__(128) float g_s    [NMAX * 64];    // lin1 scalar out  [n][u]
__device__ __align__(128) float g_v    [NMAX * 192];   // lin1 vector out  [n][i][u]  (component-major)
__device__ __align__(128) float g_sc_s [NMAX * 128];   // self-conn scalar [n][w]
__device__ __align__(128) float g_sc_v [NMAX * 192];   // self-conn vector [n][i][w]  (component-major)
// permuted agg layouts: pos p = 4*l + 2*g + c  <->  logical u = 2*l + c of group g
__device__ __align__(128) float g_s_agg[NMAX * 128];   // [n][p]      g: 0=A(u<64) 1=D
__device__ __align__(128) float g_v_agg[NMAX * 384];   // [n][i][p]   g: 0=B       1=C

// ---------------- helpers ----------------
__device__ __forceinline__ float silu_n(float x) {
    return 1.679177f * x * __fdividef(1.0f, 1.0f + __expf(-x));
}
__device__ __forceinline__ ull pack2(float x, float y) {
    ull r; asm("mov.b64 %0, {%1, %2};" : "=l"(r) : "f"(x), "f"(y)); return r;
}
__device__ __forceinline__ float2 unp2(ull a) {
    float2 r; asm("mov.b64 {%0, %1}, %2;" : "=f"(r.x), "=f"(r.y) : "l"(a)); return r;
}
__device__ __forceinline__ void ffma2(ull& d, ull a, ull b) {
    asm("fma.rn.f32x2 %0, %1, %2, %3;" : "=l"(d) : "l"(a), "l"(b), "l"(d));
}
__device__ __forceinline__ void redv4(float* p, float a, float b, float c, float d) {
    asm volatile("red.global.add.v4.f32 [%0], {%1, %2, %3, %4};"
                 :: "l"(p), "f"(a), "f"(b), "f"(c), "f"(d) : "memory");
}

// ======================= K0: zero aggregation buffers =======================
__global__ void k_zero(int n4s, int n4v) {
    int i = blockIdx.x * blockDim.x + threadIdx.x;
    float4 z = make_float4(0.f, 0.f, 0.f, 0.f);
    if (i < n4s) reinterpret_cast<float4*>(g_s_agg)[i] = z;
    if (i < n4v) reinterpret_cast<float4*>(g_v_agg)[i] = z;
}

// ======================= K1: node pre (lin1 + self-connection) ==============
// 256 threads, 16 nodes/block.  dyn smem = 82176 B.
__global__ __launch_bounds__(256, 2) void k_node_pre(
    const float* __restrict__ ns, const float* __restrict__ nv,
    const float* __restrict__ na,
    const float* __restrict__ W1s, const float* __restrict__ W1v,
    const float* __restrict__ Wscs, const float* __restrict__ Wscv)
{
    extern __shared__ float sm1[];
    float* sS    = sm1;           // 16*64         [n][k]
    float* sV    = sS + 1024;     // 16*3*64       [n][i][k]
    float* sAttr = sV + 3072;     // 16*4
    float* sAs   = sAttr + 64;    // 16*256        [n][u*4+v]
    float* sAv   = sAs + 4096;    // 16*3*256      [n][i][u*4+v]

    const int t  = threadIdx.x;
    const int n0 = blockIdx.x * 16;

    for (int i = t; i < 1024; i += 256) sS[i] = ns[(size_t)n0 * 64 + i];
    for (int i = t; i < 3072; i += 256) {
        int n = i / 192, r = i - n * 192, u = r / 3, c = r - u * 3;
        sV[n * 192 + c * 64 + u] = nv[(size_t)n0 * 192 + i];
    }
    if (t < 64) sAttr[t] = na[(size_t)n0 * 4 + t];
    __syncthreads();

    const int w = t & 63, g = t >> 6;   // 4 groups x 4 nodes

    // ---- lin1 scalar: s = ns @ W1s * (1/8) ----
    {
        float acc[4] = {0.f, 0.f, 0.f, 0.f};
        for (int k4 = 0; k4 < 64; k4 += 4) {
            float a0 = W1s[(k4 + 0) * 64 + w], a1 = W1s[(k4 + 1) * 64 + w];
            float a2 = W1s[(k4 + 2) * 64 + w], a3 = W1s[(k4 + 3) * 64 + w];
            #pragma unroll
            for (int n = 0; n < 4; n++) {
                float4 s4 = *reinterpret_cast<const float4*>(&sS[(g * 4 + n) * 64 + k4]);
                acc[n] += s4.x * a0 + s4.y * a1 + s4.z * a2 + s4.w * a3;
            }
        }
        #pragma unroll
        for (int n = 0; n < 4; n++)
            g_s[(size_t)(n0 + g * 4 + n) * 64 + w] = acc[n] * 0.125f;
    }
    // ---- lin1 vector (writes component-major) ----
    {
        float acc[4][3];
        #pragma unroll
        for (int n = 0; n < 4; n++) { acc[n][0] = acc[n][1] = acc[n][2] = 0.f; }
        for (int k4 = 0; k4 < 64; k4 += 4) {
            float a0 = W1v[(k4 + 0) * 64 + w], a1 = W1v[(k4 + 1) * 64 + w];
            float a2 = W1v[(k4 + 2) * 64 + w], a3 = W1v[(k4 + 3) * 64 + w];
            #pragma unroll
            for (int n = 0; n < 4; n++)
                #pragma unroll
                for (int i = 0; i < 3; i++) {
                    float4 s4 = *reinterpret_cast<const float4*>(&sV[(g * 4 + n) * 192 + i * 64 + k4]);
                    acc[n][i] += s4.x * a0 + s4.y * a1 + s4.z * a2 + s4.w * a3;
                }
        }
        #pragma unroll
        for (int n = 0; n < 4; n++)
            #pragma unroll
            for (int i = 0; i < 3; i++)
                g_v[(size_t)(n0 + g * 4 + n) * 192 + i * 64 + w] = acc[n][i] * 0.125f;
    }
    // ---- outer products for self-connection ----
    for (int i = t; i < 4096; i += 256) {
        int n = i >> 8, uv = i & 255;
        sAs[i] = sS[n * 64 + (uv >> 2)] * sAttr[n * 4 + (uv & 3)];
    }
    for (int i = t; i < 12288; i += 256) {
        int n = i / 768, r = i - n * 768, c = r >> 8, uv = r & 255;
        sAv[i] = sV[n * 192 + c * 64 + (uv >> 2)] * sAttr[n * 4 + (uv & 3)];
    }
    __syncthreads();

    // ---- sc_s: (16,256)@(256,128) * 1/16, ffma2 2-col ownership ----
    {
        const int cp = t & 63, g2 = t >> 6;   // col pair (2cp,2cp+1), 4 groups x 4 nodes
        ull acc[4] = {0ull, 0ull, 0ull, 0ull};
        for (int k4 = 0; k4 < 256; k4 += 4) {
            ull w0 = *reinterpret_cast<const ull*>(&Wscs[(size_t)(k4 + 0) * 128 + 2 * cp]);
            ull w1 = *reinterpret_cast<const ull*>(&Wscs[(size_t)(k4 + 1) * 128 + 2 * cp]);
            ull w2 = *reinterpret_cast<const ull*>(&Wscs[(size_t)(k4 + 2) * 128 + 2 * cp]);
            ull w3 = *reinterpret_cast<const ull*>(&Wscs[(size_t)(k4 + 3) * 128 + 2 * cp]);
            #pragma unroll
            for (int n = 0; n < 4; n++) {
                float4 a = *reinterpret_cast<const float4*>(&sAs[(g2 * 4 + n) * 256 + k4]);
                ffma2(acc[n], pack2(a.x, a.x), w0);
                ffma2(acc[n], pack2(a.y, a.y), w1);
                ffma2(acc[n], pack2(a.z, a.z), w2);
                ffma2(acc[n], pack2(a.w, a.w), w3);
            }
        }
        #pragma unroll
        for (int n = 0; n < 4; n++) {
            float2 p = unp2(acc[n]);
            *reinterpret_cast<float2*>(&g_sc_s[(size_t)(n0 + g2 * 4 + n) * 128 + 2 * cp]) =
                make_float2(p.x * 0.0625f, p.y * 0.0625f);
        }
    }
    // ---- sc_v: (48,256)@(256,64) * 1/16, ffma2, component-major out ----
    {
        const int cp = t & 31, g3 = t >> 5;   // col pair, 8 groups x 2 nodes
        ull acc[2][3];
        #pragma unroll
        for (int n = 0; n < 2; n++) { acc[n][0] = acc[n][1] = acc[n][2] = 0ull; }
        for (int k4 = 0; k4 < 256; k4 += 4) {
            ull w0 = *reinterpret_cast<const ull*>(&Wscv[(size_t)(k4 + 0) * 64 + 2 * cp]);
            ull w1 = *reinterpret_cast<const ull*>(&Wscv[(size_t)(k4 + 1) * 64 + 2 * cp]);
            ull w2 = *reinterpret_cast<const ull*>(&Wscv[(size_t)(k4 + 2) * 64 + 2 * cp]);
            ull w3 = *reinterpret_cast<const ull*>(&Wscv[(size_t)(k4 + 3) * 64 + 2 * cp]);
            #pragma unroll
            for (int n = 0; n < 2; n++)
                #pragma unroll
                for (int i = 0; i < 3; i++) {
                    float4 a = *reinterpret_cast<const float4*>(&sAv[(g3 * 2 + n) * 768 + i * 256 + k4]);
                    ffma2(acc[n][i], pack2(a.x, a.x), w0);
                    ffma2(acc[n][i], pack2(a.y, a.y), w1);
                    ffma2(acc[n][i], pack2(a.z, a.z), w2);
                    ffma2(acc[n][i], pack2(a.w, a.w), w3);
                }
        }
        #pragma unroll
        for (int n = 0; n < 2; n++)
            #pragma unroll
            for (int i = 0; i < 3; i++) {
                float2 p = unp2(acc[n][i]);
                *reinterpret_cast<float2*>(&g_sc_v[(size_t)(n0 + g3 * 2 + n) * 192 + i * 64 + 2 * cp]) =
                    make_float2(p.x * 0.0625f, p.y * 0.0625f);
            }
    }
}

// ======================= K2: edge kernel (MLP + TP + scatter) ===============
// 256 threads (8 warps); 8 edges/warp/iter.  dyn smem 100352 B.
// W2 staged column-permuted: physical p = 8*l + 2*g + c for logical col g*64+2l+c,
// pre-scaled by 1/8 (fc) * 1/16 (neigh) [* 1/sqrt3 for group D].
__global__ __launch_bounds__(256, 2) void k_edge(
    const float* __restrict__ emb, const float* __restrict__ esh,
    const int* __restrict__ esrc, const int* __restrict__ edst,
    const float* __restrict__ W0, const float* __restrict__ W1,
    const float* __restrict__ W2, int E)
{
    extern __shared__ float sm2[];
    float* sW2  = sm2;            // 16384 floats (permuted + pre-scaled)
    float* sW1  = sm2 + 16384;    // 4096  floats (pre-scaled 1/8)
    float* sW0_ = sm2 + 20480;    // 512   floats (pre-scaled 1/sqrt8)
    float* sH   = sm2 + 20992;    // 8 warps * 8 edges * 64 = 4096 floats

    const int tid = threadIdx.x;
    const float RS8 = 0.35355339059327373f;   // 1/sqrt(8)
    const float I3  = 0.5773502691896258f;    // 1/sqrt(3)
    const float SC  = 0.0078125f;             // 1/8 * 1/16
    // W2: permute + scale
    for (int idx = tid; idx < 16384; idx += 256) {
        int k = idx >> 8, c = idx & 255;
        int gg = c >> 6, u = c & 63, l = u >> 1, r = u & 1;
        int p = 8 * l + 2 * gg + r;
        float s = (gg == 3) ? SC * I3 : SC;
        sW2[k * 256 + p] = W2[idx] * s;
    }
    for (int i = tid; i < 1024; i += 256) {
        float4 v = reinterpret_cast<const float4*>(W1)[i];
        v.x *= 0.125f; v.y *= 0.125f; v.z *= 0.125f; v.w *= 0.125f;
        reinterpret_cast<float4*>(sW1)[i] = v;
    }
    for (int i = tid; i < 128; i += 256) {
        float4 v = reinterpret_cast<const float4*>(W0)[i];
        v.x *= RS8; v.y *= RS8; v.z *= RS8; v.w *= RS8;
        reinterpret_cast<float4*>(sW0_)[i] = v;
    }
    __syncthreads();

    const int warp = tid >> 5, lane = tid & 31;
    float* sHw = sH + warp * 512;

    const int noct = (E + 7) >> 3;
    for (int q = blockIdx.x * 8 + warp; q < noct; q += gridDim.x * 8) {
        const int e0 = q * 8;

        // emb: 8 edges x 8 basis -> lane holds float2 of edge (lane>>2)
        ull embp = 0ull;
        {
            int e = e0 + (lane >> 2);
            if (e < E) {
                float2 v = *reinterpret_cast<const float2*>(&emb[(size_t)e0 * 8 + 2 * lane]);
                embp = pack2(v.x, v.y);
            }
        }

        // ---- stage1: h0 = silu_n(emb @ W0') ; lane owns cols 2l,2l+1 ----
        {
            ull a1[8];
            #pragma unroll
            for (int e = 0; e < 8; e++) a1[e] = 0ull;
            #pragma unroll
            for (int kp = 0; kp < 4; kp++) {
                ull w0 = *reinterpret_cast<const ull*>(&sW0_[(2 * kp) * 64 + 2 * lane]);
                ull w1 = *reinterpret_cast<const ull*>(&sW0_[(2 * kp + 1) * 64 + 2 * lane]);
                #pragma unroll
                for (int e = 0; e < 8; e++) {
                    float2 ab = unp2(__shfl_sync(FULL, embp, e * 4 + kp));
                    ffma2(a1[e], pack2(ab.x, ab.x), w0);
                    ffma2(a1[e], pack2(ab.y, ab.y), w1);
                }
            }
            #pragma unroll
            for (int e = 0; e < 8; e++) {
                float2 p = unp2(a1[e]);
                *reinterpret_cast<float2*>(&sHw[e * 64 + 2 * lane]) =
                    make_float2(silu_n(p.x), silu_n(p.y));
            }
        }
        __syncwarp();

        // ---- stage2: h1 = silu_n(h0 @ W1') ; in-place ----
        {
            ull a2[8];
            #pragma unroll
            for (int e = 0; e < 8; e++) a2[e] = 0ull;
            #pragma unroll 4
            for (int k4 = 0; k4 < 64; k4 += 4) {
                ull wp0 = *reinterpret_cast<const ull*>(&sW1[(k4 + 0) * 64 + 2 * lane]);
                ull wp1 = *reinterpret_cast<const ull*>(&sW1[(k4 + 1) * 64 + 2 * lane]);
                ull wp2 = *reinterpret_cast<const ull*>(&sW1[(k4 + 2) * 64 + 2 * lane]);
                ull wp3 = *reinterpret_cast<const ull*>(&sW1[(k4 + 3) * 64 + 2 * lane]);
                #pragma unroll
                for (int e = 0; e < 8; e++) {
                    float4 hc = *reinterpret_cast<const float4*>(&sHw[e * 64 + k4]);
                    ffma2(a2[e], pack2(hc.x, hc.x), wp0);
                    ffma2(a2[e], pack2(hc.y, hc.y), wp1);
                    ffma2(a2[e], pack2(hc.z, hc.z), wp2);
                    ffma2(a2[e], pack2(hc.w, hc.w), wp3);
                }
            }
            __syncwarp();
            #pragma unroll
            for (int e = 0; e < 8; e++) {
                float2 p = unp2(a2[e]);
                *reinterpret_cast<float2*>(&sHw[e * 64 + 2 * lane]) =
                    make_float2(silu_n(p.x), silu_n(p.y));
            }
        }
        __syncwarp();

        // ---- stage3: w = h1 @ W2perm ; lane owns 8 permuted cols (A,B,C,D)x2 ----
        ull a3[8][4];
        #pragma unroll
        for (int e = 0; e < 8; e++)
            #pragma unroll
            for (int j = 0; j < 4; j++) a3[e][j] = 0ull;

        for (int k4 = 0; k4 < 64; k4 += 4) {
            float4 hc[8];
            #pragma unroll
            for (int e = 0; e < 8; e++)
                hc[e] = *reinterpret_cast<const float4*>(&sHw[e * 64 + k4]);
            #pragma unroll
            for (int kk = 0; kk < 4; kk++) {
                ulonglong2 wa = *reinterpret_cast<const ulonglong2*>(&sW2[(k4 + kk) * 256 + 8 * lane]);
                ulonglong2 wb = *reinterpret_cast<const ulonglong2*>(&sW2[(k4 + kk) * 256 + 8 * lane + 4]);
                #pragma unroll
                for (int e = 0; e < 8; e++) {
                    float h = (kk == 0) ? hc[e].x : (kk == 1) ? hc[e].y : (kk == 2) ? hc[e].z : hc[e].w;
                    ull hp = pack2(h, h);
                    ffma2(a3[e][0], hp, wa.x);
                    ffma2(a3[e][1], hp, wa.y);
                    ffma2(a3[e][2], hp, wb.x);
                    ffma2(a3[e][3], hp, wb.y);
                }
            }
        }

        // ---- uniform tensor product + scatter (no divergence) ----
        int src8[8], dst8[8];
        #pragma unroll
        for (int e = 0; e < 8; e++) {
            int ee = e0 + e;
            int ec = (ee < E) ? ee : 0;
            src8[e] = __ldg(&esrc[ec]);
            dst8[e] = __ldg(&edst[ec]);
        }
        #pragma unroll
        for (int e = 0; e < 8; e++) {
            int ee = e0 + e;
            float4 y;
            if (ee < E) y = __ldg(reinterpret_cast<const float4*>(&esh[(size_t)ee * 4]));
            else        y = make_float4(0.f, 0.f, 0.f, 0.f);
            const int src = src8[e], dst = dst8[e];
            float2 s2 = *reinterpret_cast<const float2*>(&g_s[(size_t)src * 64 + 2 * lane]);
            float2 vx = *reinterpret_cast<const float2*>(&g_v[(size_t)src * 192 + 0  + 2 * lane]);
            float2 vy = *reinterpret_cast<const float2*>(&g_v[(size_t)src * 192 + 64 + 2 * lane]);
            float2 vz = *reinterpret_cast<const float2*>(&g_v[(size_t)src * 192 + 128 + 2 * lane]);
            float2 wA = unp2(a3[e][0]), wB = unp2(a3[e][1]);
            float2 wC = unp2(a3[e][2]), wD = unp2(a3[e][3]);
            // oA + oD -> s_agg[dst][4l .. 4l+3]
            float d0 = vx.x * y.y + vy.x * y.z + vz.x * y.w;
            float d1 = vx.y * y.y + vy.y * y.z + vz.y * y.w;
            redv4(&g_s_agg[(size_t)dst * 128 + 4 * lane],
                  wA.x * s2.x * y.x, wA.y * s2.y * y.x, wD.x * d0, wD.y * d1);
            // oB + oC -> v_agg[dst][i][4l .. 4l+3]
            float b0 = wB.x * s2.x, b1 = wB.y * s2.y;
            float c0 = wC.x * y.x,  c1 = wC.y * y.x;
            float* pv = &g_v_agg[(size_t)dst * 384 + 4 * lane];
            redv4(pv,       b0 * y.y, b1 * y.y, c0 * vx.x, c1 * vx.y);
            redv4(pv + 128, b0 * y.z, b1 * y.z, c0 * vy.x, c1 * vy.y);
            redv4(pv + 256, b0 * y.w, b1 * y.w, c0 * vz.x, c1 * vz.y);
        }
    }
}

// ======================= K3: node post (lin2 + sc + gating) =================
// 256 threads, 16 nodes/block.  dyn smem = 40960 B.
__global__ __launch_bounds__(256, 3) void k_node_post(
    const float* __restrict__ W2s, const float* __restrict__ W2v,
    float* __restrict__ out)
{
    extern __shared__ float sm3[];
    float* sSA = sm3;          // 16*128  logical [n][k]
    float* sVA = sm3 + 2048;   // 16*3*128 logical [n][i][k]
    float* sSH = sm3 + 8192;   // 16*128

    const int t  = threadIdx.x;
    const int n0 = blockIdx.x * 16;

    // un-permute agg layouts while staging: p = 4l+2g+c -> k = g*64 + 2l + c
    for (int i = t; i < 2048; i += 256) {
        int n = i >> 7, p = i & 127;
        int l = p >> 2, qq = p & 3, gg = qq >> 1, c = qq & 1;
        sSA[n * 128 + gg * 64 + 2 * l + c] = g_s_agg[(size_t)n0 * 128 + i];
    }
    for (int i = t; i < 6144; i += 256) {
        int n = i / 384, r = i - n * 384, comp = r >> 7, p = r & 127;
        int l = p >> 2, qq = p & 3, gg = qq >> 1, c = qq & 1;
        sVA[n * 384 + comp * 128 + gg * 64 + 2 * l + c] = g_v_agg[(size_t)n0 * 384 + i];
    }
    __syncthreads();

    const float RS128 = 0.08838834764831845f;  // 1/sqrt(128)

    // ---- s_h = s_agg @ W_lin2_s * RS128 + sc_s ----
    {
        const int w2 = t & 127, g2 = t >> 7;
        float acc[8];
        #pragma unroll
        for (int n = 0; n < 8; n++) acc[n] = 0.f;
        for (int k4 = 0; k4 < 128; k4 += 4) {
            float a0 = W2s[(k4 + 0) * 128 + w2], a1 = W2s[(k4 + 1) * 128 + w2];
            float a2 = W2s[(k4 + 2) * 128 + w2], a3 = W2s[(k4 + 3) * 128 + w2];
            #pragma unroll
            for (int n = 0; n < 8; n++) {
                float4 s4 = *reinterpret_cast<const float4*>(&sSA[(g2 * 8 + n) * 128 + k4]);
                acc[n] += s4.x * a0 + s4.y * a1 + s4.z * a2 + s4.w * a3;
            }
        }
        #pragma unroll
        for (int n = 0; n < 8; n++) {
            int nn = n0 + g2 * 8 + n;
            float sh = acc[n] * RS128 + g_sc_s[(size_t)nn * 128 + w2];
            sSH[(g2 * 8 + n) * 128 + w2] = sh;
            if (w2 < 64) out[(size_t)nn * 256 + w2] = silu_n(sh);
        }
    }

    // ---- v_h = v_agg . W_lin2_v * RS128 + sc_v ----
    const int w = t & 63, g = t >> 6;
    float vh[4][3];
    #pragma unroll
    for (int n = 0; n < 4; n++) { vh[n][0] = vh[n][1] = vh[n][2] = 0.f; }
    for (int k4 = 0; k4 < 128; k4 += 4) {
        float a0 = W2v[(k4 + 0) * 64 + w], a1 = W2v[(k4 + 1) * 64 + w];
        float a2 = W2v[(k4 + 2) * 64 + w], a3 = W2v[(k4 + 3) * 64 + w];
        #pragma unroll
        for (int n = 0; n < 4; n++)
            #pragma unroll
            for (int i = 0; i < 3; i++) {
                float4 s4 = *reinterpret_cast<const float4*>(&sVA[(g * 4 + n) * 384 + i * 128 + k4]);
                vh[n][i] += s4.x * a0 + s4.y * a1 + s4.z * a2 + s4.w * a3;
            }
    }
    #pragma unroll
    for (int n = 0; n < 4; n++)
        #pragma unroll
        for (int i = 0; i < 3; i++)
            vh[n][i] = vh[n][i] * RS128 + g_sc_v[(size_t)(n0 + g * 4 + n) * 192 + i * 64 + w];
    __syncthreads();

    // ---- gated vector output ----
    #pragma unroll
    for (int n = 0; n < 4; n++) {
        int nn = n0 + g * 4 + n;
        float gate = silu_n(sSH[(g * 4 + n) * 128 + 64 + w]);
        out[(size_t)nn * 256 + 64 + w * 3 + 0] = gate * vh[n][0];
        out[(size_t)nn * 256 + 64 + w * 3 + 1] = gate * vh[n][1];
        out[(size_t)nn * 256 + 64 + w * 3 + 2] = gate * vh[n][2];
    }
}

// ======================= launcher ==========================================
extern "C" void kernel_launch(void* const* d_in, const int* in_sizes, int n_in,
                              void* d_out, int out_size) {
    const int N = in_sizes[0] / 64;
    const int E = in_sizes[3] / 4;

    const float *ns, *nv, *na, *esh, *emb;
    const float *W1s, *W1v, *W0, *W1, *W2, *W2s, *W2v, *Wscs, *Wscv;
    const int *esrc, *edst;

    ns  = (const float*)d_in[0];
    nv  = (const float*)d_in[1];
    na  = (const float*)d_in[2];
    esh = (const float*)d_in[3];
    emb = (const float*)d_in[4];
    if (in_sizes[5] == E && in_sizes[6] == E) {
        esrc = (const int*)d_in[5];  edst = (const int*)d_in[6];
        W1s  = (const float*)d_in[7];  W1v  = (const float*)d_in[8];
        W0   = (const float*)d_in[9];  W1   = (const float*)d_in[10];
        W2   = (const float*)d_in[11]; W2s  = (const float*)d_in[12];
        W2v  = (const float*)d_in[13]; Wscs = (const float*)d_in[14];
        Wscv = (const float*)d_in[15];
    } else {
        W1s  = (const float*)d_in[5];  W1v  = (const float*)d_in[6];
        W0   = (const float*)d_in[7];  W1   = (const float*)d_in[8];
        W2   = (const float*)d_in[9];  W2s  = (const float*)d_in[10];
        W2v  = (const float*)d_in[11]; Wscs = (const float*)d_in[12];
        Wscv = (const float*)d_in[13];
        esrc = (const int*)d_in[14];   edst = (const int*)d_in[15];
    }
    float* out = (float*)d_out;

    cudaFuncSetAttribute(k_edge,     cudaFuncAttributeMaxDynamicSharedMemorySize, 100352);
    cudaFuncSetAttribute(k_node_pre, cudaFuncAttributeMaxDynamicSharedMemorySize, 82176);

    int n4v = N * 96, n4s = N * 32;
    k_zero<<<(n4v + 255) / 256, 256>>>(n4s, n4v);
    k_node_pre<<<(N + 15) / 16, 256, 82176>>>(ns, nv, na, W1s, W1v, Wscs, Wscv);
    k_edge<<<296, 256, 100352>>>(emb, esh, esrc, edst, W0, W1, W2, E);
    k_node_post<<<(N + 15) / 16, 256, 40960>>>(W2s, W2v, out);
}

// round 6
// speedup vs baseline: 1.4478x; 1.0316x over previous
#include <cuda_runtime.h>
#include <cuda_bf16.h>

typedef unsigned long long ull;
#define FULL 0xffffffffu
#define NMAX 20000

// ---------------- scratch (static device globals; allocation-free) ----------
__device__ __align__(128) float g_s    [NMAX * 64];    // lin1 scalar out  [n][u]
__device__ __align__(128) float g_v    [NMAX * 192];   // lin1 vector out  [n][i][u]  (component-major)
__device__ __align__(128) float g_sc_s [NMAX * 128];   // self-conn scalar [n][w]
__device__ __align__(128) float g_sc_v [NMAX * 192];   // self-conn vector [n][i][w]  (component-major)
// permuted agg layouts: pos p = 4*l + 2*g + c  <->  logical u = 2*l + c of group g
__device__ __align__(128) float g_s_agg[NMAX * 128];   // [n][p]      g: 0=A(u<64) 1=D
__device__ __align__(128) float g_v_agg[NMAX * 384];   // [n][i][p]   g: 0=B       1=C

// ---------------- helpers ----------------
__device__ __forceinline__ float silu_n(float x) {
    return 1.679177f * x * __fdividef(1.0f, 1.0f + __expf(-x));
}
__device__ __forceinline__ ull pack2(float x, float y) {
    ull r; asm("mov.b64 %0, {%1, %2};" : "=l"(r) : "f"(x), "f"(y)); return r;
}
__device__ __forceinline__ float2 unp2(ull a) {
    float2 r; asm("mov.b64 {%0, %1}, %2;" : "=f"(r.x), "=f"(r.y) : "l"(a)); return r;
}
__device__ __forceinline__ void ffma2(ull& d, ull a, ull b) {
    asm("fma.rn.f32x2 %0, %1, %2, %3;" : "=l"(d) : "l"(a), "l"(b), "l"(d));
}
// NOTE: no "memory" clobber — red targets (g_*_agg) are disjoint from all loads
// in the kernel, and REDs commute. volatile keeps them ordered & un-deleted,
// while letting ptxas hoist the next edge's gathers above this edge's REDs.
__device__ __forceinline__ void redv4(float* p, float a, float b, float c, float d) {
    asm volatile("red.global.add.v4.f32 [%0], {%1, %2, %3, %4};"
                 :: "l"(p), "f"(a), "f"(b), "f"(c), "f"(d));
}

// ======================= K1: node pre (zero + lin1 + self-connection) =======
// 256 threads, 16 nodes/block.  dyn smem = 82176 B.
__global__ __launch_bounds__(256, 2) void k_node_pre(
    const float* __restrict__ ns, const float* __restrict__ nv,
    const float* __restrict__ na,
    const float* __restrict__ W1s, const float* __restrict__ W1v,
    const float* __restrict__ Wscs, const float* __restrict__ Wscv)
{
    extern __shared__ float sm1[];
    float* sS    = sm1;           // 16*64         [n][k]
    float* sV    = sS + 1024;     // 16*3*64       [n][i][k]
    float* sAttr = sV + 3072;     // 16*4
    float* sAs   = sAttr + 64;    // 16*256        [n][u*4+v]
    float* sAv   = sAs + 4096;    // 16*3*256      [n][i][u*4+v]

    const int t  = threadIdx.x;
    const int n0 = blockIdx.x * 16;

    // ---- zero this block's aggregation slices (replaces k_zero) ----
    {
        float4 z = make_float4(0.f, 0.f, 0.f, 0.f);
        float4* zs = reinterpret_cast<float4*>(&g_s_agg[(size_t)n0 * 128]);
        #pragma unroll
        for (int i = 0; i < 2; i++) zs[t + 256 * i] = z;          // 512 float4
        float4* zv = reinterpret_cast<float4*>(&g_v_agg[(size_t)n0 * 384]);
        #pragma unroll
        for (int i = 0; i < 6; i++) zv[t + 256 * i] = z;          // 1536 float4
    }

    for (int i = t; i < 1024; i += 256) sS[i] = ns[(size_t)n0 * 64 + i];
    for (int i = t; i < 3072; i += 256) {
        int n = i / 192, r = i - n * 192, u = r / 3, c = r - u * 3;
        sV[n * 192 + c * 64 + u] = nv[(size_t)n0 * 192 + i];
    }
    if (t < 64) sAttr[t] = na[(size_t)n0 * 4 + t];
    __syncthreads();

    const int w = t & 63, g = t >> 6;   // 4 groups x 4 nodes

    // ---- lin1 scalar: s = ns @ W1s * (1/8) ----
    {
        float acc[4] = {0.f, 0.f, 0.f, 0.f};
        for (int k4 = 0; k4 < 64; k4 += 4) {
            float a0 = W1s[(k4 + 0) * 64 + w], a1 = W1s[(k4 + 1) * 64 + w];
            float a2 = W1s[(k4 + 2) * 64 + w], a3 = W1s[(k4 + 3) * 64 + w];
            #pragma unroll
            for (int n = 0; n < 4; n++) {
                float4 s4 = *reinterpret_cast<const float4*>(&sS[(g * 4 + n) * 64 + k4]);
                acc[n] += s4.x * a0 + s4.y * a1 + s4.z * a2 + s4.w * a3;
            }
        }
        #pragma unroll
        for (int n = 0; n < 4; n++)
            g_s[(size_t)(n0 + g * 4 + n) * 64 + w] = acc[n] * 0.125f;
    }
    // ---- lin1 vector (component-major out) ----
    {
        float acc[4][3];
        #pragma unroll
        for (int n = 0; n < 4; n++) { acc[n][0] = acc[n][1] = acc[n][2] = 0.f; }
        for (int k4 = 0; k4 < 64; k4 += 4) {
            float a0 = W1v[(k4 + 0) * 64 + w], a1 = W1v[(k4 + 1) * 64 + w];
            float a2 = W1v[(k4 + 2) * 64 + w], a3 = W1v[(k4 + 3) * 64 + w];
            #pragma unroll
            for (int n = 0; n < 4; n++)
                #pragma unroll
                for (int i = 0; i < 3; i++) {
                    float4 s4 = *reinterpret_cast<const float4*>(&sV[(g * 4 + n) * 192 + i * 64 + k4]);
                    acc[n][i] += s4.x * a0 + s4.y * a1 + s4.z * a2 + s4.w * a3;
                }
        }
        #pragma unroll
        for (int n = 0; n < 4; n++)
            #pragma unroll
            for (int i = 0; i < 3; i++)
                g_v[(size_t)(n0 + g * 4 + n) * 192 + i * 64 + w] = acc[n][i] * 0.125f;
    }
    // ---- outer products for self-connection ----
    for (int i = t; i < 4096; i += 256) {
        int n = i >> 8, uv = i & 255;
        sAs[i] = sS[n * 64 + (uv >> 2)] * sAttr[n * 4 + (uv & 3)];
    }
    for (int i = t; i < 12288; i += 256) {
        int n = i / 768, r = i - n * 768, c = r >> 8, uv = r & 255;
        sAv[i] = sV[n * 192 + c * 64 + (uv >> 2)] * sAttr[n * 4 + (uv & 3)];
    }
    __syncthreads();

    // ---- sc_s: (16,256)@(256,128) * 1/16, ffma2 ----
    {
        const int cp = t & 63, g2 = t >> 6;
        ull acc[4] = {0ull, 0ull, 0ull, 0ull};
        for (int k4 = 0; k4 < 256; k4 += 4) {
            ull w0 = *reinterpret_cast<const ull*>(&Wscs[(size_t)(k4 + 0) * 128 + 2 * cp]);
            ull w1 = *reinterpret_cast<const ull*>(&Wscs[(size_t)(k4 + 1) * 128 + 2 * cp]);
            ull w2 = *reinterpret_cast<const ull*>(&Wscs[(size_t)(k4 + 2) * 128 + 2 * cp]);
            ull w3 = *reinterpret_cast<const ull*>(&Wscs[(size_t)(k4 + 3) * 128 + 2 * cp]);
            #pragma unroll
            for (int n = 0; n < 4; n++) {
                float4 a = *reinterpret_cast<const float4*>(&sAs[(g2 * 4 + n) * 256 + k4]);
                ffma2(acc[n], pack2(a.x, a.x), w0);
                ffma2(acc[n], pack2(a.y, a.y), w1);
                ffma2(acc[n], pack2(a.z, a.z), w2);
                ffma2(acc[n], pack2(a.w, a.w), w3);
            }
        }
        #pragma unroll
        for (int n = 0; n < 4; n++) {
            float2 p = unp2(acc[n]);
            *reinterpret_cast<float2*>(&g_sc_s[(size_t)(n0 + g2 * 4 + n) * 128 + 2 * cp]) =
                make_float2(p.x * 0.0625f, p.y * 0.0625f);
        }
    }
    // ---- sc_v: (48,256)@(256,64) * 1/16, ffma2, component-major out ----
    {
        const int cp = t & 31, g3 = t >> 5;
        ull acc[2][3];
        #pragma unroll
        for (int n = 0; n < 2; n++) { acc[n][0] = acc[n][1] = acc[n][2] = 0ull; }
        for (int k4 = 0; k4 < 256; k4 += 4) {
            ull w0 = *reinterpret_cast<const ull*>(&Wscv[(size_t)(k4 + 0) * 64 + 2 * cp]);
            ull w1 = *reinterpret_cast<const ull*>(&Wscv[(size_t)(k4 + 1) * 64 + 2 * cp]);
            ull w2 = *reinterpret_cast<const ull*>(&Wscv[(size_t)(k4 + 2) * 64 + 2 * cp]);
            ull w3 = *reinterpret_cast<const ull*>(&Wscv[(size_t)(k4 + 3) * 64 + 2 * cp]);
            #pragma unroll
            for (int n = 0; n < 2; n++)
                #pragma unroll
                for (int i = 0; i < 3; i++) {
                    float4 a = *reinterpret_cast<const float4*>(&sAv[(g3 * 2 + n) * 768 + i * 256 + k4]);
                    ffma2(acc[n][i], pack2(a.x, a.x), w0);
                    ffma2(acc[n][i], pack2(a.y, a.y), w1);
                    ffma2(acc[n][i], pack2(a.z, a.z), w2);
                    ffma2(acc[n][i], pack2(a.w, a.w), w3);
                }
        }
        #pragma unroll
        for (int n = 0; n < 2; n++)
            #pragma unroll
            for (int i = 0; i < 3; i++) {
                float2 p = unp2(acc[n][i]);
                *reinterpret_cast<float2*>(&g_sc_v[(size_t)(n0 + g3 * 2 + n) * 192 + i * 64 + 2 * cp]) =
                    make_float2(p.x * 0.0625f, p.y * 0.0625f);
            }
    }
}

// ======================= K2: edge kernel (MLP + TP + scatter) ===============
// 256 threads (8 warps); 8 edges/warp/iter.  dyn smem 100352 B.
__global__ __launch_bounds__(256, 2) void k_edge(
    const float* __restrict__ emb, const float* __restrict__ esh,
    const int* __restrict__ esrc, const int* __restrict__ edst,
    const float* __restrict__ W0, const float* __restrict__ W1,
    const float* __restrict__ W2, int E)
{
    extern __shared__ float sm2[];
    float* sW2  = sm2;            // 16384 floats (permuted + pre-scaled)
    float* sW1  = sm2 + 16384;    // 4096  floats (pre-scaled 1/8)
    float* sW0_ = sm2 + 20480;    // 512   floats (pre-scaled 1/sqrt8)
    float* sH   = sm2 + 20992;    // 8 warps * 8 edges * 64 = 4096 floats

    const int tid = threadIdx.x;
    const float RS8 = 0.35355339059327373f;   // 1/sqrt(8)
    const float I3  = 0.5773502691896258f;    // 1/sqrt(3)
    const float SC  = 0.0078125f;             // 1/8 * 1/16
    // W2: permute cols (p = 8l+2g+c for logical g*64+2l+c) + scale
    for (int idx = tid; idx < 16384; idx += 256) {
        int k = idx >> 8, c = idx & 255;
        int gg = c >> 6, u = c & 63, l = u >> 1, r = u & 1;
        int p = 8 * l + 2 * gg + r;
        float s = (gg == 3) ? SC * I3 : SC;
        sW2[k * 256 + p] = W2[idx] * s;
    }
    for (int i = tid; i < 1024; i += 256) {
        float4 v = reinterpret_cast<const float4*>(W1)[i];
        v.x *= 0.125f; v.y *= 0.125f; v.z *= 0.125f; v.w *= 0.125f;
        reinterpret_cast<float4*>(sW1)[i] = v;
    }
    for (int i = tid; i < 128; i += 256) {
        float4 v = reinterpret_cast<const float4*>(W0)[i];
        v.x *= RS8; v.y *= RS8; v.z *= RS8; v.w *= RS8;
        reinterpret_cast<float4*>(sW0_)[i] = v;
    }
    __syncthreads();

    const int warp = tid >> 5, lane = tid & 31;
    float* sHw = sH + warp * 512;

    const int noct = (E + 7) >> 3;
    for (int q = blockIdx.x * 8 + warp; q < noct; q += gridDim.x * 8) {
        const int e0 = q * 8;

        // emb: 8 edges x 8 basis -> lane holds float2 of edge (lane>>2)
        ull embp = 0ull;
        {
            int e = e0 + (lane >> 2);
            if (e < E) {
                float2 v = *reinterpret_cast<const float2*>(&emb[(size_t)e0 * 8 + 2 * lane]);
                embp = pack2(v.x, v.y);
            }
        }
        // edge indices early (L2-resident, cheap)
        int src8[8], dst8[8];
        #pragma unroll
        for (int e = 0; e < 8; e++) {
            int ee = e0 + e;
            int ec = (ee < E) ? ee : 0;
            src8[e] = __ldg(&esrc[ec]);
            dst8[e] = __ldg(&edst[ec]);
        }

        // ---- stage1: h0 = silu_n(emb @ W0') ; lane owns cols 2l,2l+1 ----
        {
            ull a1[8];
            #pragma unroll
            for (int e = 0; e < 8; e++) a1[e] = 0ull;
            #pragma unroll
            for (int kp = 0; kp < 4; kp++) {
                ull w0 = *reinterpret_cast<const ull*>(&sW0_[(2 * kp) * 64 + 2 * lane]);
                ull w1 = *reinterpret_cast<const ull*>(&sW0_[(2 * kp + 1) * 64 + 2 * lane]);
                #pragma unroll
                for (int e = 0; e < 8; e++) {
                    float2 ab = unp2(__shfl_sync(FULL, embp, e * 4 + kp));
                    ffma2(a1[e], pack2(ab.x, ab.x), w0);
                    ffma2(a1[e], pack2(ab.y, ab.y), w1);
                }
            }
            #pragma unroll
            for (int e = 0; e < 8; e++) {
                float2 p = unp2(a1[e]);
                *reinterpret_cast<float2*>(&sHw[e * 64 + 2 * lane]) =
                    make_float2(silu_n(p.x), silu_n(p.y));
            }
        }
        __syncwarp();

        // ---- stage2: h1 = silu_n(h0 @ W1') ; in-place ----
        {
            ull a2[8];
            #pragma unroll
            for (int e = 0; e < 8; e++) a2[e] = 0ull;
            #pragma unroll 4
            for (int k4 = 0; k4 < 64; k4 += 4) {
                ull wp0 = *reinterpret_cast<const ull*>(&sW1[(k4 + 0) * 64 + 2 * lane]);
                ull wp1 = *reinterpret_cast<const ull*>(&sW1[(k4 + 1) * 64 + 2 * lane]);
                ull wp2 = *reinterpret_cast<const ull*>(&sW1[(k4 + 2) * 64 + 2 * lane]);
                ull wp3 = *reinterpret_cast<const ull*>(&sW1[(k4 + 3) * 64 + 2 * lane]);
                #pragma unroll
                for (int e = 0; e < 8; e++) {
                    float4 hc = *reinterpret_cast<const float4*>(&sHw[e * 64 + k4]);
                    ffma2(a2[e], pack2(hc.x, hc.x), wp0);
                    ffma2(a2[e], pack2(hc.y, hc.y), wp1);
                    ffma2(a2[e], pack2(hc.z, hc.z), wp2);
                    ffma2(a2[e], pack2(hc.w, hc.w), wp3);
                }
            }
            __syncwarp();
            #pragma unroll
            for (int e = 0; e < 8; e++) {
                float2 p = unp2(a2[e]);
                *reinterpret_cast<float2*>(&sHw[e * 64 + 2 * lane]) =
                    make_float2(silu_n(p.x), silu_n(p.y));
            }
        }
        __syncwarp();

        // ---- stage3: w = h1 @ W2perm ; lane owns 8 permuted cols (A,B,C,D)x2 ----
        ull a3[8][4];
        #pragma unroll
        for (int e = 0; e < 8; e++)
            #pragma unroll
            for (int j = 0; j < 4; j++) a3[e][j] = 0ull;

        for (int k4 = 0; k4 < 64; k4 += 4) {
            float4 hc[8];
            #pragma unroll
            for (int e = 0; e < 8; e++)
                hc[e] = *reinterpret_cast<const float4*>(&sHw[e * 64 + k4]);
            #pragma unroll
            for (int kk = 0; kk < 4; kk++) {
                ulonglong2 wa = *reinterpret_cast<const ulonglong2*>(&sW2[(k4 + kk) * 256 + 8 * lane]);
                ulonglong2 wb = *reinterpret_cast<const ulonglong2*>(&sW2[(k4 + kk) * 256 + 8 * lane + 4]);
                #pragma unroll
                for (int e = 0; e < 8; e++) {
                    float h = (kk == 0) ? hc[e].x : (kk == 1) ? hc[e].y : (kk == 2) ? hc[e].z : hc[e].w;
                    ull hp = pack2(h, h);
                    ffma2(a3[e][0], hp, wa.x);
                    ffma2(a3[e][1], hp, wa.y);
                    ffma2(a3[e][2], hp, wb.x);
                    ffma2(a3[e][3], hp, wb.y);
                }
            }
        }

        // ---- uniform tensor product + scatter (REDs carry no memory clobber,
        //      so gathers of later edges overlap earlier edges' REDs) ----
        #pragma unroll
        for (int e = 0; e < 8; e++) {
            int ee = e0 + e;
            float4 y;
            if (ee < E) y = __ldg(reinterpret_cast<const float4*>(&esh[(size_t)ee * 4]));
            else        y = make_float4(0.f, 0.f, 0.f, 0.f);
            const int src = src8[e], dst = dst8[e];
            float2 s2 = __ldg(reinterpret_cast<const float2*>(&g_s[(size_t)src * 64 + 2 * lane]));
            float2 vx = __ldg(reinterpret_cast<const float2*>(&g_v[(size_t)src * 192 + 0   + 2 * lane]));
            float2 vy = __ldg(reinterpret_cast<const float2*>(&g_v[(size_t)src * 192 + 64  + 2 * lane]));
            float2 vz = __ldg(reinterpret_cast<const float2*>(&g_v[(size_t)src * 192 + 128 + 2 * lane]));
            float2 wA = unp2(a3[e][0]), wB = unp2(a3[e][1]);
            float2 wC = unp2(a3[e][2]), wD = unp2(a3[e][3]);
            // oA + oD -> s_agg[dst][4l .. 4l+3]
            float d0 = vx.x * y.y + vy.x * y.z + vz.x * y.w;
            float d1 = vx.y * y.y + vy.y * y.z + vz.y * y.w;
            redv4(&g_s_agg[(size_t)dst * 128 + 4 * lane],
                  wA.x * s2.x * y.x, wA.y * s2.y * y.x, wD.x * d0, wD.y * d1);
            // oB + oC -> v_agg[dst][i][4l .. 4l+3]
            float b0 = wB.x * s2.x, b1 = wB.y * s2.y;
            float c0 = wC.x * y.x,  c1 = wC.y * y.x;
            float* pv = &g_v_agg[(size_t)dst * 384 + 4 * lane];
            redv4(pv,       b0 * y.y, b1 * y.y, c0 * vx.x, c1 * vx.y);
            redv4(pv + 128, b0 * y.z, b1 * y.z, c0 * vy.x, c1 * vy.y);
            redv4(pv + 256, b0 * y.w, b1 * y.w, c0 * vz.x, c1 * vz.y);
        }
    }
}

// ======================= K3: node post (lin2 + sc + gating) =================
// 256 threads, 16 nodes/block.  dyn smem = 40960 B.
__global__ __launch_bounds__(256, 3) void k_node_post(
    const float* __restrict__ W2s, const float* __restrict__ W2v,
    float* __restrict__ out)
{
    extern __shared__ float sm3[];
    float* sSA = sm3;          // 16*128  logical [n][k]
    float* sVA = sm3 + 2048;   // 16*3*128 logical [n][i][k]
    float* sSH = sm3 + 8192;   // 16*128

    const int t  = threadIdx.x;
    const int n0 = blockIdx.x * 16;

    // un-permute agg layouts: p = 4l+2g+c -> k = g*64 + 2l + c
    for (int i = t; i < 2048; i += 256) {
        int n = i >> 7, p = i & 127;
        int l = p >> 2, qq = p & 3, gg = qq >> 1, c = qq & 1;
        sSA[n * 128 + gg * 64 + 2 * l + c] = g_s_agg[(size_t)n0 * 128 + i];
    }
    for (int i = t; i < 6144; i += 256) {
        int n = i / 384, r = i - n * 384, comp = r >> 7, p = r & 127;
        int l = p >> 2, qq = p & 3, gg = qq >> 1, c = qq & 1;
        sVA[n * 384 + comp * 128 + gg * 64 + 2 * l + c] = g_v_agg[(size_t)n0 * 384 + i];
    }
    __syncthreads();

    const float RS128 = 0.08838834764831845f;  // 1/sqrt(128)

    // ---- s_h = s_agg @ W_lin2_s * RS128 + sc_s  (ffma2, 2-col ownership) ----
    {
        const int cp = t & 63, g2 = t >> 6;   // cols (2cp,2cp+1); 4 groups x 4 nodes
        ull acc[4] = {0ull, 0ull, 0ull, 0ull};
        for (int k4 = 0; k4 < 128; k4 += 4) {
            ull w0 = *reinterpret_cast<const ull*>(&W2s[(size_t)(k4 + 0) * 128 + 2 * cp]);
            ull w1 = *reinterpret_cast<const ull*>(&W2s[(size_t)(k4 + 1) * 128 + 2 * cp]);
            ull w2 = *reinterpret_cast<const ull*>(&W2s[(size_t)(k4 + 2) * 128 + 2 * cp]);
            ull w3 = *reinterpret_cast<const ull*>(&W2s[(size_t)(k4 + 3) * 128 + 2 * cp]);
            #pragma unroll
            for (int n = 0; n < 4; n++) {
                float4 a = *reinterpret_cast<const float4*>(&sSA[(g2 * 4 + n) * 128 + k4]);
                ffma2(acc[n], pack2(a.x, a.x), w0);
                ffma2(acc[n], pack2(a.y, a.y), w1);
                ffma2(acc[n], pack2(a.z, a.z), w2);
                ffma2(acc[n], pack2(a.w, a.w), w3);
            }
        }
        #pragma unroll
        for (int n = 0; n < 4; n++) {
            int nn = n0 + g2 * 4 + n;
            float2 p = unp2(acc[n]);
            float2 sc = *reinterpret_cast<const float2*>(&g_sc_s[(size_t)nn * 128 + 2 * cp]);
            float2 sh = make_float2(p.x * RS128 + sc.x, p.y * RS128 + sc.y);
            *reinterpret_cast<float2*>(&sSH[(g2 * 4 + n) * 128 + 2 * cp]) = sh;
            if (cp < 32)
                *reinterpret_cast<float2*>(&out[(size_t)nn * 256 + 2 * cp]) =
                    make_float2(silu_n(sh.x), silu_n(sh.y));
        }
    }
    __syncthreads();

    // ---- v_h = v_agg @ W_lin2_v * RS128 + sc_v ; gated output (ffma2) ----
    {
        const int cp = t & 31, g3 = t >> 5;   // cols (2cp,2cp+1) of 64; 8 groups x 2 nodes
        ull acc[2][3];
        #pragma unroll
        for (int n = 0; n < 2; n++) { acc[n][0] = acc[n][1] = acc[n][2] = 0ull; }
        for (int k4 = 0; k4 < 128; k4 += 4) {
            ull w0 = *reinterpret_cast<const ull*>(&W2v[(size_t)(k4 + 0) * 64 + 2 * cp]);
            ull w1 = *reinterpret_cast<const ull*>(&W2v[(size_t)(k4 + 1) * 64 + 2 * cp]);
            ull w2 = *reinterpret_cast<const ull*>(&W2v[(size_t)(k4 + 2) * 64 + 2 * cp]);
            ull w3 = *reinterpret_cast<const ull*>(&W2v[(size_t)(k4 + 3) * 64 + 2 * cp]);
            #pragma unroll
            for (int n = 0; n < 2; n++)
                #pragma unroll
                for (int i = 0; i < 3; i++) {
                    float4 a = *reinterpret_cast<const float4*>(&sVA[(g3 * 2 + n) * 384 + i * 128 + k4]);
                    ffma2(acc[n][i], pack2(a.x, a.x), w0);
                    ffma2(acc[n][i], pack2(a.y, a.y), w1);
                    ffma2(acc[n][i], pack2(a.z, a.z), w2);
                    ffma2(acc[n][i], pack2(a.w, a.w), w3);
                }
        }
        #pragma unroll
        for (int n = 0; n < 2; n++) {
            int nn = n0 + g3 * 2 + n;
            float2 vh[3];
            #pragma unroll
            for (int i = 0; i < 3; i++) {
                float2 p = unp2(acc[n][i]);
                float2 sc = *reinterpret_cast<const float2*>(&g_sc_v[(size_t)nn * 192 + i * 64 + 2 * cp]);
                vh[i] = make_float2(p.x * RS128 + sc.x, p.y * RS128 + sc.y);
            }
            float2 gv = *reinterpret_cast<const float2*>(&sSH[(g3 * 2 + n) * 128 + 64 + 2 * cp]);
            float ga = silu_n(gv.x), gb = silu_n(gv.y);
            float* po = &out[(size_t)nn * 256 + 64 + 6 * cp];
            *reinterpret_cast<float2*>(po)     = make_float2(ga * vh[0].x, ga * vh[1].x);
            *reinterpret_cast<float2*>(po + 2) = make_float2(ga * vh[2].x, gb * vh[0].y);
            *reinterpret_cast<float2*>(po + 4) = make_float2(gb * vh[1].y, gb * vh[2].y);
        }
    }
}

// ======================= launcher ==========================================
extern "C" void kernel_launch(void* const* d_in, const int* in_sizes, int n_in,
                              void* d_out, int out_size) {
    const int N = in_sizes[0] / 64;
    const int E = in_sizes[3] / 4;

    const float *ns, *nv, *na, *esh, *emb;
    const float *W1s, *W1v, *W0, *W1, *W2, *W2s, *W2v, *Wscs, *Wscv;
    const int *esrc, *edst;

    ns  = (const float*)d_in[0];
    nv  = (const float*)d_in[1];
    na  = (const float*)d_in[2];
    esh = (const float*)d_in[3];
    emb = (const float*)d_in[4];
    if (in_sizes[5] == E && in_sizes[6] == E) {
        esrc = (const int*)d_in[5];  edst = (const int*)d_in[6];
        W1s  = (const float*)d_in[7];  W1v  = (const float*)d_in[8];
        W0   = (const float*)d_in[9];  W1   = (const float*)d_in[10];
        W2   = (const float*)d_in[11]; W2s  = (const float*)d_in[12];
        W2v  = (const float*)d_in[13]; Wscs = (const float*)d_in[14];
        Wscv = (const float*)d_in[15];
    } else {
        W1s  = (const float*)d_in[5];  W1v  = (const float*)d_in[6];
        W0   = (const float*)d_in[7];  W1   = (const float*)d_in[8];
        W2   = (const float*)d_in[9];  W2s  = (const float*)d_in[10];
        W2v  = (const float*)d_in[11]; Wscs = (const float*)d_in[12];
        Wscv = (const float*)d_in[13];
        esrc = (const int*)d_in[14];   edst = (const int*)d_in[15];
    }
    float* out = (float*)d_out;

    cudaFuncSetAttribute(k_edge,     cudaFuncAttributeMaxDynamicSharedMemorySize, 100352);
    cudaFuncSetAttribute(k_node_pre, cudaFuncAttributeMaxDynamicSharedMemorySize, 82176);

    k_node_pre<<<(N + 15) / 16, 256, 82176>>>(ns, nv, na, W1s, W1v, Wscs, Wscv);
    k_edge<<<296, 256, 100352>>>(emb, esh, esrc, edst, W0, W1, W2, E);
    k_node_post<<<(N + 15) / 16, 256, 40960>>>(W2s, W2v, out);
}

// round 8
// speedup vs baseline: 1.5306x; 1.0572x over previous
#include <cuda_runtime.h>
#include <cuda_bf16.h>

typedef unsigned long long ull;
#define FULL 0xffffffffu
#define NMAX 20000

// ---------------- scratch (static device globals; allocation-free) ----------
__device__ __align__(128) float g_s    [NMAX * 64];    // lin1 scalar out  [n][u]
__device__ __align__(128) float g_v    [NMAX * 192];   // lin1 vector out  [n][i][u]  (component-major)
__device__ __align__(128) float g_sc_s [NMAX * 128];   // self-conn scalar [n][w]
__device__ __align__(128) float g_sc_v [NMAX * 192];   // self-conn vector [n][i][w]  (component-major)
// permuted agg layouts: pos p = 4*l + 2*g + c  <->  logical u = 2*l + c of group g
__device__ __align__(128) float g_s_agg[NMAX * 128];   // [n][p]      g: 0=A(u<64) 1=D
__device__ __align__(128) float g_v_agg[NMAX * 384];   // [n][i][p]   g: 0=B       1=C

// ---------------- helpers ----------------
__device__ __forceinline__ float silu_n(float x) {
    return 1.679177f * x * __fdividef(1.0f, 1.0f + __expf(-x));
}
__device__ __forceinline__ ull pack2(float x, float y) {
    ull r; asm("mov.b64 %0, {%1, %2};" : "=l"(r) : "f"(x), "f"(y)); return r;
}
__device__ __forceinline__ float2 unp2(ull a) {
    float2 r; asm("mov.b64 {%0, %1}, %2;" : "=f"(r.x), "=f"(r.y) : "l"(a)); return r;
}
__device__ __forceinline__ void ffma2(ull& d, ull a, ull b) {
    asm("fma.rn.f32x2 %0, %1, %2, %3;" : "=l"(d) : "l"(a), "l"(b), "l"(d));
}
// no "memory" clobber — see R6 note: targets disjoint from all loads, REDs commute
__device__ __forceinline__ void redv4(float* p, float a, float b, float c, float d) {
    asm volatile("red.global.add.v4.f32 [%0], {%1, %2, %3, %4};"
                 :: "l"(p), "f"(a), "f"(b), "f"(c), "f"(d));
}

// ======================= K1: node pre (zero + lin1 + self-connection) =======
// 256 threads, 16 nodes/block.  static smem ~16.6 KB.
__global__ __launch_bounds__(256, 3) void k_node_pre(
    const float* __restrict__ ns, const float* __restrict__ nv,
    const float* __restrict__ na,
    const float* __restrict__ W1s, const float* __restrict__ W1v,
    const float* __restrict__ Wscs, const float* __restrict__ Wscv)
{
    __shared__ float sS[1024];     // [n][k]
    __shared__ float sV[3072];     // [n][i][k]
    __shared__ float sAttr[64];

    const int t  = threadIdx.x;
    const int n0 = blockIdx.x * 16;

    // ---- zero this block's aggregation slices ----
    {
        float4 z = make_float4(0.f, 0.f, 0.f, 0.f);
        float4* zs = reinterpret_cast<float4*>(&g_s_agg[(size_t)n0 * 128]);
        #pragma unroll
        for (int i = 0; i < 2; i++) zs[t + 256 * i] = z;
        float4* zv = reinterpret_cast<float4*>(&g_v_agg[(size_t)n0 * 384]);
        #pragma unroll
        for (int i = 0; i < 6; i++) zv[t + 256 * i] = z;
    }

    for (int i = t; i < 1024; i += 256) sS[i] = ns[(size_t)n0 * 64 + i];
    for (int i = t; i < 3072; i += 256) {
        int n = i / 192, r = i - n * 192, u = r / 3, c = r - u * 3;
        sV[n * 192 + c * 64 + u] = nv[(size_t)n0 * 192 + i];
    }
    if (t < 64) sAttr[t] = na[(size_t)n0 * 4 + t];
    __syncthreads();

    const int w = t & 63, g = t >> 6;   // 4 groups x 4 nodes (lin1 mapping)

    // ---- lin1 scalar: s = ns @ W1s * (1/8) ----
    {
        float acc[4] = {0.f, 0.f, 0.f, 0.f};
        for (int k4 = 0; k4 < 64; k4 += 4) {
            float a0 = W1s[(k4 + 0) * 64 + w], a1 = W1s[(k4 + 1) * 64 + w];
            float a2 = W1s[(k4 + 2) * 64 + w], a3 = W1s[(k4 + 3) * 64 + w];
            #pragma unroll
            for (int n = 0; n < 4; n++) {
                float4 s4 = *reinterpret_cast<const float4*>(&sS[(g * 4 + n) * 64 + k4]);
                acc[n] += s4.x * a0 + s4.y * a1 + s4.z * a2 + s4.w * a3;
            }
        }
        #pragma unroll
        for (int n = 0; n < 4; n++)
            g_s[(size_t)(n0 + g * 4 + n) * 64 + w] = acc[n] * 0.125f;
    }
    // ---- lin1 vector (component-major out) ----
    {
        float acc[4][3];
        #pragma unroll
        for (int n = 0; n < 4; n++) { acc[n][0] = acc[n][1] = acc[n][2] = 0.f; }
        for (int k4 = 0; k4 < 64; k4 += 4) {
            float a0 = W1v[(k4 + 0) * 64 + w], a1 = W1v[(k4 + 1) * 64 + w];
            float a2 = W1v[(k4 + 2) * 64 + w], a3 = W1v[(k4 + 3) * 64 + w];
            #pragma unroll
            for (int n = 0; n < 4; n++)
                #pragma unroll
                for (int i = 0; i < 3; i++) {
                    float4 s4 = *reinterpret_cast<const float4*>(&sV[(g * 4 + n) * 192 + i * 64 + k4]);
                    acc[n][i] += s4.x * a0 + s4.y * a1 + s4.z * a2 + s4.w * a3;
                }
        }
        #pragma unroll
        for (int n = 0; n < 4; n++)
            #pragma unroll
            for (int i = 0; i < 3; i++)
                g_v[(size_t)(n0 + g * 4 + n) * 192 + i * 64 + w] = acc[n][i] * 0.125f;
    }

    // ---- sc_s: on-the-fly A = s x attr ; 4-col ownership; LDG.128 weights ----
    // cq = t&31 -> cols 4cq..4cq+3 of 128 ; ng = t>>5 -> nodes 2ng, 2ng+1
    {
        const int cq = t & 31, ng = t >> 5;
        const int nA = 2 * ng, nB = nA + 1;
        float aA[4], aB[4];
        #pragma unroll
        for (int v = 0; v < 4; v++) { aA[v] = sAttr[nA * 4 + v]; aB[v] = sAttr[nB * 4 + v]; }
        ull accA[2] = {0ull, 0ull}, accB[2] = {0ull, 0ull};
        for (int u = 0; u < 64; u++) {
            float s0 = sS[nA * 64 + u];      // broadcast LDS (warp-uniform)
            float s1 = sS[nB * 64 + u];
            #pragma unroll
            for (int v = 0; v < 4; v++) {
                ulonglong2 wq = *reinterpret_cast<const ulonglong2*>(
                    &Wscs[(size_t)(4 * u + v) * 128 + 4 * cq]);
                float tA = s0 * aA[v], tB = s1 * aB[v];
                ull pA = pack2(tA, tA), pB = pack2(tB, tB);
                ffma2(accA[0], pA, wq.x); ffma2(accA[1], pA, wq.y);
                ffma2(accB[0], pB, wq.x); ffma2(accB[1], pB, wq.y);
            }
        }
        float2 a0 = unp2(accA[0]), a1 = unp2(accA[1]);
        float2 b0 = unp2(accB[0]), b1 = unp2(accB[1]);
        *reinterpret_cast<float4*>(&g_sc_s[(size_t)(n0 + nA) * 128 + 4 * cq]) =
            make_float4(a0.x * 0.0625f, a0.y * 0.0625f, a1.x * 0.0625f, a1.y * 0.0625f);
        *reinterpret_cast<float4*>(&g_sc_s[(size_t)(n0 + nB) * 128 + 4 * cq]) =
            make_float4(b0.x * 0.0625f, b0.y * 0.0625f, b1.x * 0.0625f, b1.y * 0.0625f);
    }

    // ---- sc_v: cq = t&15 -> cols 4cq..4cq+3 of 64 ; n = t>>4 (one node, 3 comps) ----
    {
        const int cq = t & 15, n = t >> 4;
        float at[4];
        #pragma unroll
        for (int v = 0; v < 4; v++) at[v] = sAttr[n * 4 + v];
        ull acc[3][2];
        #pragma unroll
        for (int i = 0; i < 3; i++) { acc[i][0] = 0ull; acc[i][1] = 0ull; }
        for (int u = 0; u < 64; u++) {
            float sx = sV[n * 192 + u];
            float sy = sV[n * 192 + 64 + u];
            float sz = sV[n * 192 + 128 + u];
            #pragma unroll
            for (int v = 0; v < 4; v++) {
                ulonglong2 wq = *reinterpret_cast<const ulonglong2*>(
                    &Wscv[(size_t)(4 * u + v) * 64 + 4 * cq]);
                float tx = sx * at[v], ty = sy * at[v], tz = sz * at[v];
                ull px = pack2(tx, tx), py = pack2(ty, ty), pz = pack2(tz, tz);
                ffma2(acc[0][0], px, wq.x); ffma2(acc[0][1], px, wq.y);
                ffma2(acc[1][0], py, wq.x); ffma2(acc[1][1], py, wq.y);
                ffma2(acc[2][0], pz, wq.x); ffma2(acc[2][1], pz, wq.y);
            }
        }
        #pragma unroll
        for (int i = 0; i < 3; i++) {
            float2 p0 = unp2(acc[i][0]), p1 = unp2(acc[i][1]);
            *reinterpret_cast<float4*>(&g_sc_v[(size_t)(n0 + n) * 192 + i * 64 + 4 * cq]) =
                make_float4(p0.x * 0.0625f, p0.y * 0.0625f, p1.x * 0.0625f, p1.y * 0.0625f);
        }
    }
}

// ======================= K2: edge kernel (MLP + TP + scatter) ===============
// 256 threads (8 warps); 8 edges/warp/iter.  dyn smem 100352 B.
__global__ __launch_bounds__(256, 2) void k_edge(
    const float* __restrict__ emb, const float* __restrict__ esh,
    const int* __restrict__ esrc, const int* __restrict__ edst,
    const float* __restrict__ W0, const float* __restrict__ W1,
    const float* __restrict__ W2, int E)
{
    extern __shared__ float sm2[];
    float* sW2  = sm2;            // 16384 floats (permuted + pre-scaled)
    float* sW1  = sm2 + 16384;    // 4096  floats (pre-scaled 1/8)
    float* sW0_ = sm2 + 20480;    // 512   floats (pre-scaled 1/sqrt8)
    float* sH   = sm2 + 20992;    // 8 warps * 8 edges * 64 = 4096 floats

    const int tid = threadIdx.x;
    const float RS8 = 0.35355339059327373f;   // 1/sqrt(8)
    const float I3  = 0.5773502691896258f;    // 1/sqrt(3)
    const float SC  = 0.0078125f;             // 1/8 * 1/16
    for (int idx = tid; idx < 16384; idx += 256) {
        int k = idx >> 8, c = idx & 255;
        int gg = c >> 6, u = c & 63, l = u >> 1, r = u & 1;
        int p = 8 * l + 2 * gg + r;
        float s = (gg == 3) ? SC * I3 : SC;
        sW2[k * 256 + p] = W2[idx] * s;
    }
    for (int i = tid; i < 1024; i += 256) {
        float4 v = reinterpret_cast<const float4*>(W1)[i];
        v.x *= 0.125f; v.y *= 0.125f; v.z *= 0.125f; v.w *= 0.125f;
        reinterpret_cast<float4*>(sW1)[i] = v;
    }
    for (int i = tid; i < 128; i += 256) {
        float4 v = reinterpret_cast<const float4*>(W0)[i];
        v.x *= RS8; v.y *= RS8; v.z *= RS8; v.w *= RS8;
        reinterpret_cast<float4*>(sW0_)[i] = v;
    }
    __syncthreads();

    const int warp = tid >> 5, lane = tid & 31;
    float* sHw = sH + warp * 512;

    const int noct = (E + 7) >> 3;
    for (int q = blockIdx.x * 8 + warp; q < noct; q += gridDim.x * 8) {
        const int e0 = q * 8;

        ull embp = 0ull;
        {
            int e = e0 + (lane >> 2);
            if (e < E) {
                float2 v = *reinterpret_cast<const float2*>(&emb[(size_t)e0 * 8 + 2 * lane]);
                embp = pack2(v.x, v.y);
            }
        }
        int src8[8], dst8[8];
        #pragma unroll
        for (int e = 0; e < 8; e++) {
            int ee = e0 + e;
            int ec = (ee < E) ? ee : 0;
            src8[e] = __ldg(&esrc[ec]);
            dst8[e] = __ldg(&edst[ec]);
        }

        // ---- stage1 ----
        {
            ull a1[8];
            #pragma unroll
            for (int e = 0; e < 8; e++) a1[e] = 0ull;
            #pragma unroll
            for (int kp = 0; kp < 4; kp++) {
                ull w0 = *reinterpret_cast<const ull*>(&sW0_[(2 * kp) * 64 + 2 * lane]);
                ull w1 = *reinterpret_cast<const ull*>(&sW0_[(2 * kp + 1) * 64 + 2 * lane]);
                #pragma unroll
                for (int e = 0; e < 8; e++) {
                    float2 ab = unp2(__shfl_sync(FULL, embp, e * 4 + kp));
                    ffma2(a1[e], pack2(ab.x, ab.x), w0);
                    ffma2(a1[e], pack2(ab.y, ab.y), w1);
                }
            }
            #pragma unroll
            for (int e = 0; e < 8; e++) {
                float2 p = unp2(a1[e]);
                *reinterpret_cast<float2*>(&sHw[e * 64 + 2 * lane]) =
                    make_float2(silu_n(p.x), silu_n(p.y));
            }
        }
        __syncwarp();

        // ---- stage2 ----
        {
            ull a2[8];
            #pragma unroll
            for (int e = 0; e < 8; e++) a2[e] = 0ull;
            #pragma unroll 4
            for (int k4 = 0; k4 < 64; k4 += 4) {
                ull wp0 = *reinterpret_cast<const ull*>(&sW1[(k4 + 0) * 64 + 2 * lane]);
                ull wp1 = *reinterpret_cast<const ull*>(&sW1[(k4 + 1) * 64 + 2 * lane]);
                ull wp2 = *reinterpret_cast<const ull*>(&sW1[(k4 + 2) * 64 + 2 * lane]);
                ull wp3 = *reinterpret_cast<const ull*>(&sW1[(k4 + 3) * 64 + 2 * lane]);
                #pragma unroll
                for (int e = 0; e < 8; e++) {
                    float4 hc = *reinterpret_cast<const float4*>(&sHw[e * 64 + k4]);
                    ffma2(a2[e], pack2(hc.x, hc.x), wp0);
                    ffma2(a2[e], pack2(hc.y, hc.y), wp1);
                    ffma2(a2[e], pack2(hc.z, hc.z), wp2);
                    ffma2(a2[e], pack2(hc.w, hc.w), wp3);
                }
            }
            __syncwarp();
            #pragma unroll
            for (int e = 0; e < 8; e++) {
                float2 p = unp2(a2[e]);
                *reinterpret_cast<float2*>(&sHw[e * 64 + 2 * lane]) =
                    make_float2(silu_n(p.x), silu_n(p.y));
            }
        }
        __syncwarp();

        // ---- stage3 ----
        ull a3[8][4];
        #pragma unroll
        for (int e = 0; e < 8; e++)
            #pragma unroll
            for (int j = 0; j < 4; j++) a3[e][j] = 0ull;

        for (int k4 = 0; k4 < 64; k4 += 4) {
            float4 hc[8];
            #pragma unroll
            for (int e = 0; e < 8; e++)
                hc[e] = *reinterpret_cast<const float4*>(&sHw[e * 64 + k4]);
            #pragma unroll
            for (int kk = 0; kk < 4; kk++) {
                ulonglong2 wa = *reinterpret_cast<const ulonglong2*>(&sW2[(k4 + kk) * 256 + 8 * lane]);
                ulonglong2 wb = *reinterpret_cast<const ulonglong2*>(&sW2[(k4 + kk) * 256 + 8 * lane + 4]);
                #pragma unroll
                for (int e = 0; e < 8; e++) {
                    float h = (kk == 0) ? hc[e].x : (kk == 1) ? hc[e].y : (kk == 2) ? hc[e].z : hc[e].w;
                    ull hp = pack2(h, h);
                    ffma2(a3[e][0], hp, wa.x);
                    ffma2(a3[e][1], hp, wa.y);
                    ffma2(a3[e][2], hp, wb.x);
                    ffma2(a3[e][3], hp, wb.y);
                }
            }
        }

        // ---- uniform tensor product + scatter ----
        #pragma unroll
        for (int e = 0; e < 8; e++) {
            int ee = e0 + e;
            float4 y;
            if (ee < E) y = __ldg(reinterpret_cast<const float4*>(&esh[(size_t)ee * 4]));
            else        y = make_float4(0.f, 0.f, 0.f, 0.f);
            const int src = src8[e], dst = dst8[e];
            float2 s2 = __ldg(reinterpret_cast<const float2*>(&g_s[(size_t)src * 64 + 2 * lane]));
            float2 vx = __ldg(reinterpret_cast<const float2*>(&g_v[(size_t)src * 192 + 0   + 2 * lane]));
            float2 vy = __ldg(reinterpret_cast<const float2*>(&g_v[(size_t)src * 192 + 64  + 2 * lane]));
            float2 vz = __ldg(reinterpret_cast<const float2*>(&g_v[(size_t)src * 192 + 128 + 2 * lane]));
            float2 wA = unp2(a3[e][0]), wB = unp2(a3[e][1]);
            float2 wC = unp2(a3[e][2]), wD = unp2(a3[e][3]);
            float d0 = vx.x * y.y + vy.x * y.z + vz.x * y.w;
            float d1 = vx.y * y.y + vy.y * y.z + vz.y * y.w;
            redv4(&g_s_agg[(size_t)dst * 128 + 4 * lane],
                  wA.x * s2.x * y.x, wA.y * s2.y * y.x, wD.x * d0, wD.y * d1);
            float b0 = wB.x * s2.x, b1 = wB.y * s2.y;
            float c0 = wC.x * y.x,  c1 = wC.y * y.x;
            float* pv = &g_v_agg[(size_t)dst * 384 + 4 * lane];
            redv4(pv,       b0 * y.y, b1 * y.y, c0 * vx.x, c1 * vx.y);
            redv4(pv + 128, b0 * y.z, b1 * y.z, c0 * vy.x, c1 * vy.y);
            redv4(pv + 256, b0 * y.w, b1 * y.w, c0 * vz.x, c1 * vz.y);
        }
    }
}

// ======================= K3: node post (lin2 + sc + gating) =================
// 256 threads, 16 nodes/block.  static smem 40 KB.
__global__ __launch_bounds__(256, 3) void k_node_post(
    const float* __restrict__ W2s, const float* __restrict__ W2v,
    float* __restrict__ out)
{
    __shared__ float sSA[2048];    // logical [n][k]     (16*128)
    __shared__ float sVA[6144];    // logical [n][i][k]  (16*3*128)
    __shared__ float sSH[2048];    // s_h staging

    const int t  = threadIdx.x;
    const int n0 = blockIdx.x * 16;

    // un-permute agg layouts: p = 4l+2g+c -> k = g*64 + 2l + c
    for (int i = t; i < 2048; i += 256) {
        int n = i >> 7, p = i & 127;
        int l = p >> 2, qq = p & 3, gg = qq >> 1, c = qq & 1;
        sSA[n * 128 + gg * 64 + 2 * l + c] = g_s_agg[(size_t)n0 * 128 + i];
    }
    for (int i = t; i < 6144; i += 256) {
        int n = i / 384, r = i - n * 384, comp = r >> 7, p = r & 127;
        int l = p >> 2, qq = p & 3, gg = qq >> 1, c = qq & 1;
        sVA[n * 384 + comp * 128 + gg * 64 + 2 * l + c] = g_v_agg[(size_t)n0 * 384 + i];
    }
    __syncthreads();

    const float RS128 = 0.08838834764831845f;  // 1/sqrt(128)

    // ---- s_h = s_agg @ W_lin2_s * RS128 + sc_s ; 4-col ownership ----
    // cq = t&31 -> cols 4cq..4cq+3 of 128 ; ng = t>>5 -> nodes 2ng, 2ng+1
    {
        const int cq = t & 31, ng = t >> 5;
        const int nA = 2 * ng, nB = nA + 1;
        ull accA[2] = {0ull, 0ull}, accB[2] = {0ull, 0ull};
        for (int k = 0; k < 128; k++) {
            ulonglong2 wq = *reinterpret_cast<const ulonglong2*>(&W2s[(size_t)k * 128 + 4 * cq]);
            float sA = sSA[nA * 128 + k];   // broadcast LDS
            float sB = sSA[nB * 128 + k];
            ull pA = pack2(sA, sA), pB = pack2(sB, sB);
            ffma2(accA[0], pA, wq.x); ffma2(accA[1], pA, wq.y);
            ffma2(accB[0], pB, wq.x); ffma2(accB[1], pB, wq.y);
        }
        #pragma unroll
        for (int nn = 0; nn < 2; nn++) {
            int node = (nn == 0) ? nA : nB;
            ull* acc = (nn == 0) ? accA : accB;
            int gn = n0 + node;
            float2 p0 = unp2(acc[0]), p1 = unp2(acc[1]);
            float4 sc = *reinterpret_cast<const float4*>(&g_sc_s[(size_t)gn * 128 + 4 * cq]);
            float4 sh = make_float4(p0.x * RS128 + sc.x, p0.y * RS128 + sc.y,
                                    p1.x * RS128 + sc.z, p1.y * RS128 + sc.w);
            *reinterpret_cast<float4*>(&sSH[node * 128 + 4 * cq]) = sh;
            if (cq < 16)
                *reinterpret_cast<float4*>(&out[(size_t)gn * 256 + 4 * cq]) =
                    make_float4(silu_n(sh.x), silu_n(sh.y), silu_n(sh.z), silu_n(sh.w));
        }
    }
    __syncthreads();

    // ---- v_h = v_agg @ W_lin2_v * RS128 + sc_v ; gated output ----
    // cq = t&15 -> cols 4cq..4cq+3 of 64 ; n = t>>4 (one node, 3 comps)
    {
        const int cq = t & 15, n = t >> 4;
        const int gn = n0 + n;
        ull acc[3][2];
        #pragma unroll
        for (int i = 0; i < 3; i++) { acc[i][0] = 0ull; acc[i][1] = 0ull; }
        for (int k = 0; k < 128; k++) {
            ulonglong2 wq = *reinterpret_cast<const ulonglong2*>(&W2v[(size_t)k * 64 + 4 * cq]);
            float sx = sVA[n * 384 + k];
            float sy = sVA[n * 384 + 128 + k];
            float sz = sVA[n * 384 + 256 + k];
            ull px = pack2(sx, sx), py = pack2(sy, sy), pz = pack2(sz, sz);
            ffma2(acc[0][0], px, wq.x); ffma2(acc[0][1], px, wq.y);
            ffma2(acc[1][0], py, wq.x); ffma2(acc[1][1], py, wq.y);
            ffma2(acc[2][0], pz, wq.x); ffma2(acc[2][1], pz, wq.y);
        }
        // vh[col j][comp i]; cols j = 4cq + j
        float vh[4][3];
        #pragma unroll
        for (int i = 0; i < 3; i++) {
            float2 p0 = unp2(acc[i][0]), p1 = unp2(acc[i][1]);
            float4 sc = *reinterpret_cast<const float4*>(&g_sc_v[(size_t)gn * 192 + i * 64 + 4 * cq]);
            vh[0][i] = p0.x * RS128 + sc.x;
            vh[1][i] = p0.y * RS128 + sc.y;
            vh[2][i] = p1.x * RS128 + sc.z;
            vh[3][i] = p1.y * RS128 + sc.w;
        }
        float4 gv = *reinterpret_cast<const float4*>(&sSH[n * 128 + 64 + 4 * cq]);
        float g0 = silu_n(gv.x), g1 = silu_n(gv.y), g2 = silu_n(gv.z), g3 = silu_n(gv.w);
        float* po = &out[(size_t)gn * 256 + 64 + 12 * cq];
        *reinterpret_cast<float4*>(po) =
            make_float4(g0 * vh[0][0], g0 * vh[0][1], g0 * vh[0][2], g1 * vh[1][0]);
        *reinterpret_cast<float4*>(po + 4) =
            make_float4(g1 * vh[1][1], g1 * vh[1][2], g2 * vh[2][0], g2 * vh[2][1]);
        *reinterpret_cast<float4*>(po + 8) =
            make_float4(g2 * vh[2][2], g3 * vh[3][0], g3 * vh[3][1], g3 * vh[3][2]);
    }
}

// ======================= launcher ==========================================
extern "C" void kernel_launch(void* const* d_in, const int* in_sizes, int n_in,
                              void* d_out, int out_size) {
    const int N = in_sizes[0] / 64;
    const int E = in_sizes[3] / 4;

    const float *ns, *nv, *na, *esh, *emb;
    const float *W1s, *W1v, *W0, *W1, *W2, *W2s, *W2v, *Wscs, *Wscv;
    const int *esrc, *edst;

    ns  = (const float*)d_in[0];
    nv  = (const float*)d_in[1];
    na  = (const float*)d_in[2];
    esh = (const float*)d_in[3];
    emb = (const float*)d_in[4];
    if (in_sizes[5] == E && in_sizes[6] == E) {
        esrc = (const int*)d_in[5];  edst = (const int*)d_in[6];
        W1s  = (const float*)d_in[7];  W1v  = (const float*)d_in[8];
        W0   = (const float*)d_in[9];  W1   = (const float*)d_in[10];
        W2   = (const float*)d_in[11]; W2s  = (const float*)d_in[12];
        W2v  = (const float*)d_in[13]; Wscs = (const float*)d_in[14];
        Wscv = (const float*)d_in[15];
    } else {
        W1s  = (const float*)d_in[5];  W1v  = (const float*)d_in[6];
        W0   = (const float*)d_in[7];  W1   = (const float*)d_in[8];
        W2   = (const float*)d_in[9];  W2s  = (const float*)d_in[10];
        W2v  = (const float*)d_in[11]; Wscs = (const float*)d_in[12];
        Wscv = (const float*)d_in[13];
        esrc = (const int*)d_in[14];   edst = (const int*)d_in[15];
    }
    float* out = (float*)d_out;

    cudaFuncSetAttribute(k_edge, cudaFuncAttributeMaxDynamicSharedMemorySize, 100352);

    k_node_pre<<<(N + 15) / 16, 256>>>(ns, nv, na, W1s, W1v, Wscs, Wscv);
    k_edge<<<296, 256, 100352>>>(emb, esh, esrc, edst, W0, W1, W2, E);
    k_node_post<<<(N + 15) / 16, 256>>>(W2s, W2v, out);
}